// round 10
// baseline (speedup 1.0000x reference)
#include <cuda_runtime.h>
#include <cuda_bf16.h>
#include <cstdint>
#include <math.h>

#define BS   2
#define LEN  11253
#define MROWS (BS*LEN)   // 22506
#define D    256
#define NH   8
#define NP   4
#define NL   4
#define DH   32
#define DFF  1024

// ---- scratch (device globals; no allocation allowed) ----
__device__ __nv_bfloat16  g_valb   [(size_t)MROWS * D];
__device__ __nv_bfloat16  g_srcb   [(size_t)MROWS * D];
__device__ __nv_bfloat16  g_attnb  [(size_t)MROWS * D];
__device__ float          g_x      [(size_t)MROWS * D];
__device__ __nv_bfloat16  g_xr     [(size_t)MROWS * D];
__device__ __nv_bfloat16  g_hid    [(size_t)MROWS * DFF];
__device__ float          g_attw   [(size_t)MROWS * NH * NP];
__device__ float          g_offs   [(size_t)MROWS * NH * NP * 2];
__device__ __nv_bfloat16  g_WvT    [D * D];
__device__ __nv_bfloat16  g_WoT    [D * D];
__device__ __nv_bfloat16  g_W1T    [DFF * D];
__device__ __nv_bfloat16  g_W2T    [D * DFF];

// =====================================================================
// helpers
// =====================================================================
__device__ __forceinline__ void mma_bf16(float* d, const uint32_t* a, const uint32_t* b) {
    asm volatile(
        "mma.sync.aligned.m16n8k16.row.col.f32.bf16.bf16.f32 "
        "{%0,%1,%2,%3}, {%4,%5,%6,%7}, {%8,%9}, {%0,%1,%2,%3};"
        : "+f"(d[0]), "+f"(d[1]), "+f"(d[2]), "+f"(d[3])
        : "r"(a[0]), "r"(a[1]), "r"(a[2]), "r"(a[3]), "r"(b[0]), "r"(b[1]));
}
__device__ __forceinline__ void ldsm_x4(uint32_t* r, uint32_t addr) {
    asm volatile("ldmatrix.sync.aligned.m8n8.x4.shared.b16 {%0,%1,%2,%3}, [%4];"
        : "=r"(r[0]), "=r"(r[1]), "=r"(r[2]), "=r"(r[3]) : "r"(addr));
}
__device__ __forceinline__ uint32_t smem_addr_u32(const void* p) {
    uint32_t a;
    asm("{ .reg .u64 t; cvta.to.shared.u64 t, %1; cvt.u32.u64 %0, t; }" : "=r"(a) : "l"(p));
    return a;
}

// =====================================================================
// BF16 tensor-core GEMM (plain): C = A @ BT^T + bias, opt relu, bf16 out.
// 128x128 CTA tile, BK=32, 3-stage cp.async, 8 warps (2m x 4n),
// 64x32 warp tile, ldmatrix, 2 CTAs/SM.
// =====================================================================
#define SSTR        40
#define TILE_B      (128*SSTR*2)          // 10240
#define STAGE_B     (2*TILE_B)            // 20480
#define GEMM_SMEM   (3*STAGE_B)           // 61440

template<int RELU>
__global__ void __launch_bounds__(256, 2)
gemm_bf(const __nv_bfloat16* __restrict__ A, const __nv_bfloat16* __restrict__ BT,
        const float* __restrict__ bias, __nv_bfloat16* __restrict__ Cb,
        int M, int N, int K)
{
    extern __shared__ __align__(16) char smem[];
    int tid = threadIdx.x, wid = tid >> 5, lane = tid & 31;
    int g = lane >> 2, qc = lane & 3;
    int row0 = blockIdx.y * 128, col0 = blockIdx.x * 128;
    int wm = (wid & 1) * 64, wn = (wid >> 1) * 32;

    uint32_t smem_u = smem_addr_u32(smem);
    const int NC = K >> 5;

    auto load_chunk = [&](int c) {
        if (c >= NC) { asm volatile("cp.async.commit_group;"); return; }
        uint32_t a_st = smem_u + (c % 3) * STAGE_B;
        uint32_t b_st = a_st + TILE_B;
        int k0 = c * 32;
        const __nv_bfloat16* Ab = A + (size_t)row0 * K + k0;
        const __nv_bfloat16* Bb = BT + (size_t)col0 * K + k0;
#pragma unroll
        for (int i = 0; i < 2; i++) {
            int f4 = tid + i * 256;
            int r = f4 >> 2, seg = f4 & 3;
            uint32_t off = (uint32_t)(r * 80 + seg * 16);
            uint32_t nbytes = (row0 + r < M) ? 16u : 0u;
            asm volatile("cp.async.cg.shared.global [%0], [%1], 16, %2;"
                :: "r"(a_st + off), "l"(Ab + (size_t)r * K + seg * 8), "r"(nbytes));
            asm volatile("cp.async.cg.shared.global [%0], [%1], 16;"
                :: "r"(b_st + off), "l"(Bb + (size_t)r * K + seg * 8));
        }
        asm volatile("cp.async.commit_group;");
    };

    float acc[4][4][4];
#pragma unroll
    for (int mt = 0; mt < 4; mt++)
#pragma unroll
        for (int nt = 0; nt < 4; nt++)
#pragma unroll
            for (int i = 0; i < 4; i++) acc[mt][nt][i] = 0.0f;

    int sub = lane >> 3, rr = lane & 7;
    uint32_t a_lrow = (uint32_t)(wm + (sub & 1) * 8 + rr);
    uint32_t a_koff = (uint32_t)((sub >> 1) * 16);
    uint32_t b_lrow = (uint32_t)(wn + (sub >> 1) * 8 + rr);
    uint32_t b_koff = (uint32_t)((sub & 1) * 16);

    load_chunk(0);
    load_chunk(1);

    for (int c = 0; c < NC; c++) {
        asm volatile("cp.async.wait_group 1;");
        __syncthreads();
        load_chunk(c + 2);

        uint32_t a_base = smem_u + (c % 3) * STAGE_B;
        uint32_t b_base = a_base + TILE_B;
#pragma unroll
        for (int ks = 0; ks < 2; ks++) {
            uint32_t kb = (uint32_t)(ks * 32);
            uint32_t af[4][4];
#pragma unroll
            for (int mt = 0; mt < 4; mt++)
                ldsm_x4(af[mt], a_base + (a_lrow + mt * 16) * 80 + kb + a_koff);
            uint32_t bf[4][2];
#pragma unroll
            for (int pr = 0; pr < 2; pr++) {
                uint32_t t4[4];
                ldsm_x4(t4, b_base + (b_lrow + pr * 16) * 80 + kb + b_koff);
                bf[pr * 2 + 0][0] = t4[0]; bf[pr * 2 + 0][1] = t4[1];
                bf[pr * 2 + 1][0] = t4[2]; bf[pr * 2 + 1][1] = t4[3];
            }
#pragma unroll
            for (int mt = 0; mt < 4; mt++)
#pragma unroll
                for (int nt = 0; nt < 4; nt++)
                    mma_bf16(acc[mt][nt], af[mt], bf[nt]);
        }
    }

#pragma unroll
    for (int mt = 0; mt < 4; mt++) {
        int r0 = row0 + wm + mt * 16 + g;
#pragma unroll
        for (int nt = 0; nt < 4; nt++) {
            int col = col0 + wn + nt * 8 + 2 * qc;
            float b0 = bias[col], b1 = bias[col + 1];
#pragma unroll
            for (int half = 0; half < 2; half++) {
                int rrow = r0 + half * 8;
                if (rrow < M) {
                    float vx = acc[mt][nt][half * 2 + 0] + b0;
                    float vy = acc[mt][nt][half * 2 + 1] + b1;
                    if (RELU) { vx = fmaxf(vx, 0.f); vy = fmaxf(vy, 0.f); }
                    __nv_bfloat162 v2 = __floats2bfloat162_rn(vx, vy);
                    *(__nv_bfloat162*)(Cb + (size_t)rrow * N + col) = v2;
                }
            }
        }
    }
}

// =====================================================================
// Fused BF16 GEMM + residual + LayerNorm:
// out = LN(A @ BT^T + bias + res) * g + b   (N fixed = 256, full row)
// CTA tile 64x256 (8 warps 2m x 4n, 32x64 warp tile). grid = M/64.
// WRB: also write bf16 copy of out.
// =====================================================================
#define F_TILE_A   (64*80)                // 5120
#define F_TILE_B   (256*80)               // 20480
#define F_STAGE    (F_TILE_A + F_TILE_B)  // 25600
#define FLN_SMEM   (3*F_STAGE)            // 76800

template<int WRB>
__global__ void __launch_bounds__(256, 2)
gemm_ln(const __nv_bfloat16* __restrict__ A, const __nv_bfloat16* __restrict__ BT,
        const float* __restrict__ bias, const float* __restrict__ res,
        const float* __restrict__ lng, const float* __restrict__ lnb,
        float* __restrict__ out, __nv_bfloat16* __restrict__ out_b,
        int M, int K)
{
    extern __shared__ __align__(16) char smem[];
    __shared__ float ps[64][4], pq[64][4];
    __shared__ float sbias[256], sg[256], sb[256];

    int tid = threadIdx.x, wid = tid >> 5, lane = tid & 31;
    int g = lane >> 2, qc = lane & 3;
    int row0 = blockIdx.x * 64;
    int wm = (wid & 1) * 32, wn = (wid >> 1) * 64;
    int nw = wid >> 1;

    sbias[tid] = bias[tid];
    sg[tid] = lng[tid];
    sb[tid] = lnb[tid];

    uint32_t smem_u = smem_addr_u32(smem);
    const int NC = K >> 5;

    auto load_chunk = [&](int c) {
        if (c >= NC) { asm volatile("cp.async.commit_group;"); return; }
        uint32_t a_st = smem_u + (c % 3) * F_STAGE;
        uint32_t b_st = a_st + F_TILE_A;
        int k0 = c * 32;
        const __nv_bfloat16* Ab = A + (size_t)row0 * K + k0;
        const __nv_bfloat16* Bb = BT + k0;
        {   // A: 256 segs, 1 per thread
            int r = tid >> 2, seg = tid & 3;
            uint32_t off = (uint32_t)(r * 80 + seg * 16);
            uint32_t nbytes = (row0 + r < M) ? 16u : 0u;
            asm volatile("cp.async.cg.shared.global [%0], [%1], 16, %2;"
                :: "r"(a_st + off), "l"(Ab + (size_t)r * K + seg * 8), "r"(nbytes));
        }
#pragma unroll
        for (int i = 0; i < 4; i++) {  // B: 1024 segs, 4 per thread
            int f4 = tid + i * 256;
            int r = f4 >> 2, seg = f4 & 3;
            uint32_t off = (uint32_t)(r * 80 + seg * 16);
            asm volatile("cp.async.cg.shared.global [%0], [%1], 16;"
                :: "r"(b_st + off), "l"(Bb + (size_t)r * K + seg * 8));
        }
        asm volatile("cp.async.commit_group;");
    };

    float acc[2][8][4];
#pragma unroll
    for (int mt = 0; mt < 2; mt++)
#pragma unroll
        for (int nt = 0; nt < 8; nt++)
#pragma unroll
            for (int i = 0; i < 4; i++) acc[mt][nt][i] = 0.0f;

    int sub = lane >> 3, rr = lane & 7;
    uint32_t a_lrow = (uint32_t)(wm + (sub & 1) * 8 + rr);
    uint32_t a_koff = (uint32_t)((sub >> 1) * 16);
    uint32_t b_lrow = (uint32_t)(wn + (sub >> 1) * 8 + rr);
    uint32_t b_koff = (uint32_t)((sub & 1) * 16);

    load_chunk(0);
    load_chunk(1);

    for (int c = 0; c < NC; c++) {
        asm volatile("cp.async.wait_group 1;");
        __syncthreads();
        load_chunk(c + 2);

        uint32_t a_base = smem_u + (c % 3) * F_STAGE;
        uint32_t b_base = a_base + F_TILE_A;
#pragma unroll
        for (int ks = 0; ks < 2; ks++) {
            uint32_t kb = (uint32_t)(ks * 32);
            uint32_t af[2][4];
#pragma unroll
            for (int mt = 0; mt < 2; mt++)
                ldsm_x4(af[mt], a_base + (a_lrow + mt * 16) * 80 + kb + a_koff);
            uint32_t bf[8][2];
#pragma unroll
            for (int pr = 0; pr < 4; pr++) {
                uint32_t t4[4];
                ldsm_x4(t4, b_base + (b_lrow + pr * 16) * 80 + kb + b_koff);
                bf[pr * 2 + 0][0] = t4[0]; bf[pr * 2 + 0][1] = t4[1];
                bf[pr * 2 + 1][0] = t4[2]; bf[pr * 2 + 1][1] = t4[3];
            }
#pragma unroll
            for (int mt = 0; mt < 2; mt++)
#pragma unroll
                for (int nt = 0; nt < 8; nt++)
                    mma_bf16(acc[mt][nt], af[mt], bf[nt]);
        }
    }

    // ---- epilogue pass 1: v = acc + bias + res; partial row sums ----
#pragma unroll
    for (int mt = 0; mt < 2; mt++) {
#pragma unroll
        for (int half = 0; half < 2; half++) {
            int rl = wm + mt * 16 + half * 8 + g;
            int row = row0 + rl;
            bool ok = row < M;
            float s = 0.f, u = 0.f;
#pragma unroll
            for (int nt = 0; nt < 8; nt++) {
                int cl = wn + nt * 8 + 2 * qc;
                float2 rv = make_float2(0.f, 0.f);
                if (ok) rv = *(const float2*)(res + (size_t)row * 256 + cl);
                float vx = acc[mt][nt][half * 2 + 0] + sbias[cl] + rv.x;
                float vy = acc[mt][nt][half * 2 + 1] + sbias[cl + 1] + rv.y;
                acc[mt][nt][half * 2 + 0] = vx;
                acc[mt][nt][half * 2 + 1] = vy;
                s += vx + vy;
                u += vx * vx + vy * vy;
            }
            s += __shfl_xor_sync(0xffffffffu, s, 1);
            s += __shfl_xor_sync(0xffffffffu, s, 2);
            u += __shfl_xor_sync(0xffffffffu, u, 1);
            u += __shfl_xor_sync(0xffffffffu, u, 2);
            if (qc == 0) { ps[rl][nw] = s; pq[rl][nw] = u; }
        }
    }
    __syncthreads();

    // ---- epilogue pass 2: normalize + store ----
#pragma unroll
    for (int mt = 0; mt < 2; mt++) {
#pragma unroll
        for (int half = 0; half < 2; half++) {
            int rl = wm + mt * 16 + half * 8 + g;
            int row = row0 + rl;
            if (row >= M) continue;
            float sum = ps[rl][0] + ps[rl][1] + ps[rl][2] + ps[rl][3];
            float sq  = pq[rl][0] + pq[rl][1] + pq[rl][2] + pq[rl][3];
            float mean = sum * (1.0f / 256.0f);
            float var  = sq * (1.0f / 256.0f) - mean * mean;
            float rs = rsqrtf(var + 1e-5f);
#pragma unroll
            for (int nt = 0; nt < 8; nt++) {
                int cl = wn + nt * 8 + 2 * qc;
                float ox = (acc[mt][nt][half * 2 + 0] - mean) * rs * sg[cl] + sb[cl];
                float oy = (acc[mt][nt][half * 2 + 1] - mean) * rs * sg[cl + 1] + sb[cl + 1];
                *(float2*)(out + (size_t)row * 256 + cl) = make_float2(ox, oy);
                if (WRB) {
                    __nv_bfloat162 v2 = __floats2bfloat162_rn(ox, oy);
                    *(__nv_bfloat162*)(out_b + (size_t)row * 256 + cl) = v2;
                }
            }
        }
    }
}

// =====================================================================
// Fused prep: weight transposes -> bf16, src -> bf16, topk.
// =====================================================================
#define PREP_T_BLK   640
#define PREP_F_BLK   5627
#define PREP_K_BLK   704
#define PREP_BLOCKS  (PREP_T_BLK + PREP_F_BLK + PREP_K_BLK)

__global__ void __launch_bounds__(256)
prep_kernel(const float* __restrict__ src,
            const float* __restrict__ Wv, const float* __restrict__ Wo,
            const float* __restrict__ W1, const float* __restrict__ W2,
            const float* __restrict__ m0, const float* __restrict__ m1,
            const float* __restrict__ m2, const float* __restrict__ m3,
            const float* __restrict__ pmw, const float* __restrict__ pmb,
            __nv_bfloat16* __restrict__ WvT, __nv_bfloat16* __restrict__ WoT,
            __nv_bfloat16* __restrict__ W1T, __nv_bfloat16* __restrict__ W2T,
            __nv_bfloat16* __restrict__ srcb)
{
    int bid = blockIdx.x;
    int tid = threadIdx.x;

    if (bid < PREP_T_BLK) {
        __shared__ float t[32][33];
        const float* s; __nv_bfloat16* dst; int R, C, bx, by;
        if (bid < 64)       { s = Wv; dst = WvT; R = 256;  C = 256;  int u = bid;       bx = u & 7;  by = u >> 3; }
        else if (bid < 128) { s = Wo; dst = WoT; R = 256;  C = 256;  int u = bid - 64;  bx = u & 7;  by = u >> 3; }
        else if (bid < 384) { s = W1; dst = W1T; R = 256;  C = 1024; int u = bid - 128; bx = u & 31; by = u >> 5; }
        else                { s = W2; dst = W2T; R = 1024; C = 256;  int u = bid - 384; bx = u & 7;  by = u >> 3; }
        bx *= 32; by *= 32;
        int tx = tid & 31, ty = tid >> 5;
#pragma unroll
        for (int i = 0; i < 32; i += 8)
            t[ty + i][tx] = s[(size_t)(by + ty + i) * C + bx + tx];
        __syncthreads();
#pragma unroll
        for (int i = 0; i < 32; i += 8)
            dst[(size_t)(bx + ty + i) * R + by + tx] = __float2bfloat16(t[tx][ty + i]);
        return;
    }
    if (bid < PREP_T_BLK + PREP_F_BLK) {
        int i = (bid - PREP_T_BLK) * 256 + tid;
        const int n4 = MROWS * D / 4;
        if (i < n4) {
            float4 v = ((const float4*)src)[i];
            ((__nv_bfloat162*)srcb)[2 * i + 0] = __floats2bfloat162_rn(v.x, v.y);
            ((__nv_bfloat162*)srcb)[2 * i + 1] = __floats2bfloat162_rn(v.z, v.w);
        }
        return;
    }
    int t = (bid - PREP_T_BLK - PREP_F_BLK) * 256 + tid;
    if (t >= MROWS * NH) return;
    int h = t % NH;
    int r = t / NH;
    int q = r % LEN;
    int b = r / LEN;

    int l, Wl, s0;
    const float* mk;
    if (q < 8464)        { l = 0; Wl = 92; s0 = 0;     mk = m0; }
    else if (q < 10580)  { l = 1; Wl = 46; s0 = 8464;  mk = m1; }
    else if (q < 11109)  { l = 2; Wl = 23; s0 = 10580; mk = m2; }
    else                 { l = 3; Wl = 12; s0 = 11109; mk = m3; }
    int Hl = Wl;
    int pos = q - s0;
    int y = pos / Wl, x = pos % Wl;

    float w  = pmw[l * NH + h];
    float bb = pmb[l * NH + h];
    const float* mb = mk + (size_t)b * Hl * Wl;

    float tv[4] = {-1e30f, -1e30f, -1e30f, -1e30f};
    int   ti[4] = {0, 0, 0, 0};

    for (int i = 0; i < 7; i++) {
        int yy = y + i - 3;
        for (int j = 0; j < 7; j++) {
            int xx = x + j - 3;
            float val = 0.0f;
            if (yy >= 0 && yy < Hl && xx >= 0 && xx < Wl)
                val = fmaf(mb[yy * Wl + xx], w, bb);
            if (val > tv[3]) {
                int k = i * 7 + j;
                tv[3] = val; ti[3] = k;
                if (tv[3] > tv[2]) { float fv = tv[2]; tv[2] = tv[3]; tv[3] = fv; int iv = ti[2]; ti[2] = ti[3]; ti[3] = iv; }
                if (tv[2] > tv[1]) { float fv = tv[1]; tv[1] = tv[2]; tv[2] = fv; int iv = ti[1]; ti[1] = ti[2]; ti[2] = iv; }
                if (tv[1] > tv[0]) { float fv = tv[0]; tv[0] = tv[1]; tv[1] = fv; int iv = ti[0]; ti[0] = ti[1]; ti[1] = iv; }
            }
        }
    }

    float mx = tv[0];
    float e0 = expf(tv[0] - mx), e1 = expf(tv[1] - mx),
          e2 = expf(tv[2] - mx), e3 = expf(tv[3] - mx);
    float inv = 1.0f / (4.0f * (e0 + e1 + e2 + e3));

    int base = (r * NH + h) * NP;
    float ee[4] = {e0, e1, e2, e3};
#pragma unroll
    for (int p = 0; p < 4; p++) {
        g_attw[base + p] = ee[p] * inv;
        g_offs[(size_t)(base + p) * 2 + 0] = (float)(ti[p] % 7 - 3);
        g_offs[(size_t)(base + p) * 2 + 1] = (float)(ti[p] / 7 - 3);
    }
}

// =====================================================================
// Deformable sampling: warp = (query, head), bf16 value gathers.
// =====================================================================
__global__ void __launch_bounds__(256)
sample_kernel(const float* __restrict__ ref)
{
    __shared__ int2 s_d[8][16][4];

    int r = blockIdx.x;
    int wid = threadIdx.x >> 5, lane = threadIdx.x & 31;
    int b = r / LEN;

    if (lane < 16) {
        const int HsA[4] = {92, 46, 23, 12};
        const int S0A[4] = {0, 8464, 10580, 11109};
        int l = lane >> 2, p = lane & 3;
        int Wi = HsA[l];
        float Wf = (float)Wi;

        float rx = ref[(size_t)(r * NL + l) * 2 + 0];
        float ry = ref[(size_t)(r * NL + l) * 2 + 1];
        int base = (r * NH + wid) * NP + p;
        float wgt = g_attw[base];
        float ox  = g_offs[(size_t)base * 2 + 0];
        float oy  = g_offs[(size_t)base * 2 + 1];

        float locx = rx + ox / Wf;
        float locy = ry + oy / Wf;
        float xf = locx * Wf - 0.5f;
        float yf = locy * Wf - 0.5f;
        float x0f = floorf(xf), y0f = floorf(yf);
        float tx = xf - x0f, ty = yf - y0f;
        int x0 = (int)x0f, y0 = (int)y0f;
        int x1 = x0 + 1,  y1 = y0 + 1;

        float w00 = (1.0f - tx) * (1.0f - ty) * wgt;
        float w01 = tx * (1.0f - ty) * wgt;
        float w10 = (1.0f - tx) * ty * wgt;
        float w11 = tx * ty * wgt;

        bool vx0 = (x0 >= 0) & (x0 < Wi);
        bool vx1 = (x1 >= 0) & (x1 < Wi);
        bool vy0 = (y0 >= 0) & (y0 < Wi);
        bool vy1 = (y1 >= 0) & (y1 < Wi);

        int x0c = min(max(x0, 0), Wi - 1), x1c = min(max(x1, 0), Wi - 1);
        int y0c = min(max(y0, 0), Wi - 1), y1c = min(max(y1, 0), Wi - 1);
        int rb = b * LEN + S0A[l];

        s_d[wid][lane][0] = make_int2(rb + y0c * Wi + x0c, __float_as_int((vy0 & vx0) ? w00 : 0.0f));
        s_d[wid][lane][1] = make_int2(rb + y0c * Wi + x1c, __float_as_int((vy0 & vx1) ? w01 : 0.0f));
        s_d[wid][lane][2] = make_int2(rb + y1c * Wi + x0c, __float_as_int((vy1 & vx0) ? w10 : 0.0f));
        s_d[wid][lane][3] = make_int2(rb + y1c * Wi + x1c, __float_as_int((vy1 & vx1) ? w11 : 0.0f));
    }
    __syncwarp();

    int j  = lane >> 3;
    int cq = lane & 7;
    const __nv_bfloat16* vb = g_valb + wid * DH + cq * 4;

    float ax = 0.f, ay = 0.f, az = 0.f, aw = 0.f;
#pragma unroll
    for (int c = 0; c < 16; c++) {
        int2 d = s_d[wid][c][j];
        float w = __int_as_float(d.y);
        uint2 raw = *(const uint2*)(vb + (size_t)d.x * D);
        float2 f0 = __bfloat1622float2(*(__nv_bfloat162*)&raw.x);
        float2 f1 = __bfloat1622float2(*(__nv_bfloat162*)&raw.y);
        ax = fmaf(w, f0.x, ax);
        ay = fmaf(w, f0.y, ay);
        az = fmaf(w, f1.x, az);
        aw = fmaf(w, f1.y, aw);
    }
#pragma unroll
    for (int o = 8; o <= 16; o <<= 1) {
        ax += __shfl_xor_sync(0xffffffffu, ax, o);
        ay += __shfl_xor_sync(0xffffffffu, ay, o);
        az += __shfl_xor_sync(0xffffffffu, az, o);
        aw += __shfl_xor_sync(0xffffffffu, aw, o);
    }
    if (lane < 8) {
        __nv_bfloat162 p0 = __floats2bfloat162_rn(ax, ay);
        __nv_bfloat162 p1 = __floats2bfloat162_rn(az, aw);
        uint2 st;
        st.x = *(uint32_t*)&p0;
        st.y = *(uint32_t*)&p1;
        *(uint2*)(g_attnb + (size_t)r * D + wid * DH + cq * 4) = st;
    }
}

// =====================================================================
extern "C" void kernel_launch(void* const* d_in, const int* in_sizes, int n_in,
                              void* d_out, int out_size)
{
    const float* src  = (const float*)d_in[0];
    const float* ref  = (const float*)d_in[2];
    const float* m0   = (const float*)d_in[4];
    const float* m1   = (const float*)d_in[5];
    const float* m2   = (const float*)d_in[6];
    const float* m3   = (const float*)d_in[7];
    const float* pmw  = (const float*)d_in[10];
    const float* pmb  = (const float*)d_in[11];
    const float* Wv   = (const float*)d_in[12];
    const float* bv   = (const float*)d_in[13];
    const float* Wo   = (const float*)d_in[14];
    const float* bo   = (const float*)d_in[15];
    const float* ln1g = (const float*)d_in[16];
    const float* ln1b = (const float*)d_in[17];
    const float* W1   = (const float*)d_in[18];
    const float* b1   = (const float*)d_in[19];
    const float* W2   = (const float*)d_in[20];
    const float* b2   = (const float*)d_in[21];
    const float* ln2g = (const float*)d_in[22];
    const float* ln2b = (const float*)d_in[23];
    float* out = (float*)d_out;

    float *px;
    __nv_bfloat16 *pvb, *psb, *pab, *pxr, *ph, *pWvT, *pWoT, *pW1T, *pW2T;
    cudaGetSymbolAddress((void**)&pvb,  g_valb);
    cudaGetSymbolAddress((void**)&psb,  g_srcb);
    cudaGetSymbolAddress((void**)&pab,  g_attnb);
    cudaGetSymbolAddress((void**)&px,   g_x);
    cudaGetSymbolAddress((void**)&pxr,  g_xr);
    cudaGetSymbolAddress((void**)&ph,   g_hid);
    cudaGetSymbolAddress((void**)&pWvT, g_WvT);
    cudaGetSymbolAddress((void**)&pWoT, g_WoT);
    cudaGetSymbolAddress((void**)&pW1T, g_W1T);
    cudaGetSymbolAddress((void**)&pW2T, g_W2T);

    cudaFuncSetAttribute((const void*)gemm_bf<0>, cudaFuncAttributeMaxDynamicSharedMemorySize, GEMM_SMEM);
    cudaFuncSetAttribute((const void*)gemm_bf<1>, cudaFuncAttributeMaxDynamicSharedMemorySize, GEMM_SMEM);
    cudaFuncSetAttribute((const void*)gemm_ln<0>, cudaFuncAttributeMaxDynamicSharedMemorySize, FLN_SMEM);
    cudaFuncSetAttribute((const void*)gemm_ln<1>, cudaFuncAttributeMaxDynamicSharedMemorySize, FLN_SMEM);

    const int MB  = (MROWS + 127) / 128;  // 176
    const int FB  = (MROWS + 63) / 64;    // 352

    // 0. fused prep: weight transposes + src->bf16 + topk
    prep_kernel<<<PREP_BLOCKS, 256>>>(src, Wv, Wo, W1, W2, m0, m1, m2, m3,
                                      pmw, pmb, pWvT, pWoT, pW1T, pW2T, psb);

    // 1. value = src @ Wv + bv  -> bf16
    gemm_bf<0><<<dim3(2, MB), 256, GEMM_SMEM>>>(psb, pWvT, bv, pvb, MROWS, 256, 256);

    // 2. deformable bilinear sampling -> bf16 attnout
    sample_kernel<<<MROWS, 256>>>(ref);

    // 3. x = LN(src + attnout @ Wo + bo)  [fused GEMM+LN], fp32 + bf16
    gemm_ln<1><<<FB, 256, FLN_SMEM>>>(pab, pWoT, bo, src, ln1g, ln1b,
                                      px, pxr, MROWS, 256);

    // 4. hid = relu(x @ W1 + b1) -> bf16
    gemm_bf<1><<<dim3(8, MB), 256, GEMM_SMEM>>>(pxr, pW1T, b1, ph, MROWS, 1024, 256);

    // 5. out = LN(x + hid @ W2 + b2)  [fused GEMM+LN]
    gemm_ln<0><<<FB, 256, FLN_SMEM>>>(ph, pW2T, b2, px, ln2g, ln2b,
                                      out, nullptr, MROWS, 1024);
}

// round 11
// speedup vs baseline: 1.0257x; 1.0257x over previous
#include <cuda_runtime.h>
#include <cuda_bf16.h>
#include <cstdint>
#include <math.h>

#define BS   2
#define LEN  11253
#define MROWS (BS*LEN)   // 22506
#define D    256
#define NH   8
#define NP   4
#define NL   4
#define DH   32
#define DFF  1024

// ---- scratch (device globals; no allocation allowed) ----
__device__ __nv_bfloat16  g_valb   [(size_t)MROWS * D];
__device__ __nv_bfloat16  g_srcb   [(size_t)MROWS * D];
__device__ __nv_bfloat16  g_attnb  [(size_t)MROWS * D];
__device__ float          g_tmp    [(size_t)MROWS * D];
__device__ float          g_x      [(size_t)MROWS * D];
__device__ __nv_bfloat16  g_xr     [(size_t)MROWS * D];
__device__ __nv_bfloat16  g_hid    [(size_t)MROWS * DFF];
__device__ float          g_attw   [(size_t)MROWS * NH * NP];
__device__ float          g_offs   [(size_t)MROWS * NH * NP * 2];
__device__ __nv_bfloat16  g_WvT    [D * D];
__device__ __nv_bfloat16  g_WoT    [D * D];
__device__ __nv_bfloat16  g_W1T    [DFF * D];
__device__ __nv_bfloat16  g_W2T    [D * DFF];

// =====================================================================
// helpers
// =====================================================================
__device__ __forceinline__ void mma_bf16(float* d, const uint32_t* a, const uint32_t* b) {
    asm volatile(
        "mma.sync.aligned.m16n8k16.row.col.f32.bf16.bf16.f32 "
        "{%0,%1,%2,%3}, {%4,%5,%6,%7}, {%8,%9}, {%0,%1,%2,%3};"
        : "+f"(d[0]), "+f"(d[1]), "+f"(d[2]), "+f"(d[3])
        : "r"(a[0]), "r"(a[1]), "r"(a[2]), "r"(a[3]), "r"(b[0]), "r"(b[1]));
}
__device__ __forceinline__ void ldsm_x4(uint32_t* r, uint32_t addr) {
    asm volatile("ldmatrix.sync.aligned.m8n8.x4.shared.b16 {%0,%1,%2,%3}, [%4];"
        : "=r"(r[0]), "=r"(r[1]), "=r"(r[2]), "=r"(r[3]) : "r"(addr));
}
__device__ __forceinline__ uint32_t smem_addr_u32(const void* p) {
    uint32_t a;
    asm("{ .reg .u64 t; cvta.to.shared.u64 t, %1; cvt.u32.u64 %0, t; }" : "=r"(a) : "l"(p));
    return a;
}

// =====================================================================
// BF16 tensor-core GEMM: C = A @ BT^T + bias (opt relu; fp32 or bf16 out)
// 128x128 CTA tile, BK=64, 3-stage cp.async, 8 warps (2m x 4n),
// 64x32 warp tile, ldmatrix, 2 CTAs/SM.
// Smem rows: 64 bf16 data + 8 pad = stride 72 bf16 (144B). ldmatrix rows
// land on banks 4r..4r+3 -> all 32 banks over 8 rows, conflict-free.
// =====================================================================
#define SSTR        72                    // bf16 units per smem row
#define ROWB        144                   // bytes per smem row
#define TILE_B      (128*ROWB)            // 18432
#define STAGE_B     (2*TILE_B)            // 36864
#define GEMM_SMEM   (3*STAGE_B)           // 110592

template<int RELU, int OUTBF16>
__global__ void __launch_bounds__(256, 2)
gemm_bf(const __nv_bfloat16* __restrict__ A, const __nv_bfloat16* __restrict__ BT,
        const float* __restrict__ bias, void* __restrict__ Cv,
        int M, int N, int K)
{
    extern __shared__ __align__(16) char smem[];
    int tid = threadIdx.x, wid = tid >> 5, lane = tid & 31;
    int g = lane >> 2, qc = lane & 3;
    int row0 = blockIdx.y * 128, col0 = blockIdx.x * 128;
    int wm = (wid & 1) * 64, wn = (wid >> 1) * 32;

    uint32_t smem_u = smem_addr_u32(smem);
    const int NC = K >> 6;     // 64-K chunks

    auto load_chunk = [&](int c) {
        if (c >= NC) { asm volatile("cp.async.commit_group;"); return; }
        uint32_t a_st = smem_u + (c % 3) * STAGE_B;
        uint32_t b_st = a_st + TILE_B;
        int k0 = c * 64;
        const __nv_bfloat16* Ab = A + (size_t)row0 * K + k0;
        const __nv_bfloat16* Bb = BT + (size_t)col0 * K + k0;
#pragma unroll
        for (int i = 0; i < 4; i++) {
            int f4 = tid + i * 256;           // 1024 16B-segments per tile
            int r = f4 >> 3, seg = f4 & 7;
            uint32_t off = (uint32_t)(r * ROWB + seg * 16);
            uint32_t nbytes = (row0 + r < M) ? 16u : 0u;
            asm volatile("cp.async.cg.shared.global [%0], [%1], 16, %2;"
                :: "r"(a_st + off), "l"(Ab + (size_t)r * K + seg * 8), "r"(nbytes));
            asm volatile("cp.async.cg.shared.global [%0], [%1], 16;"
                :: "r"(b_st + off), "l"(Bb + (size_t)r * K + seg * 8));
        }
        asm volatile("cp.async.commit_group;");
    };

    float acc[4][4][4];
#pragma unroll
    for (int mt = 0; mt < 4; mt++)
#pragma unroll
        for (int nt = 0; nt < 4; nt++)
#pragma unroll
            for (int i = 0; i < 4; i++) acc[mt][nt][i] = 0.0f;

    int sub = lane >> 3, rr = lane & 7;
    uint32_t a_lrow = (uint32_t)(wm + (sub & 1) * 8 + rr);
    uint32_t a_koff = (uint32_t)((sub >> 1) * 16);
    uint32_t b_lrow = (uint32_t)(wn + (sub >> 1) * 8 + rr);
    uint32_t b_koff = (uint32_t)((sub & 1) * 16);

    load_chunk(0);
    load_chunk(1);

    for (int c = 0; c < NC; c++) {
        if (c + 1 < NC) asm volatile("cp.async.wait_group 1;");
        else            asm volatile("cp.async.wait_group 0;");
        __syncthreads();
        load_chunk(c + 2);

        uint32_t a_base = smem_u + (c % 3) * STAGE_B;
        uint32_t b_base = a_base + TILE_B;
#pragma unroll
        for (int ks = 0; ks < 4; ks++) {      // 4 k-steps of 16 per 64-chunk
            uint32_t kb = (uint32_t)(ks * 32);
            uint32_t af[4][4];
#pragma unroll
            for (int mt = 0; mt < 4; mt++)
                ldsm_x4(af[mt], a_base + (a_lrow + mt * 16) * ROWB + kb + a_koff);
            uint32_t bf[4][2];
#pragma unroll
            for (int pr = 0; pr < 2; pr++) {
                uint32_t t4[4];
                ldsm_x4(t4, b_base + (b_lrow + pr * 16) * ROWB + kb + b_koff);
                bf[pr * 2 + 0][0] = t4[0]; bf[pr * 2 + 0][1] = t4[1];
                bf[pr * 2 + 1][0] = t4[2]; bf[pr * 2 + 1][1] = t4[3];
            }
#pragma unroll
            for (int mt = 0; mt < 4; mt++)
#pragma unroll
                for (int nt = 0; nt < 4; nt++)
                    mma_bf16(acc[mt][nt], af[mt], bf[nt]);
        }
    }

    // epilogue
#pragma unroll
    for (int mt = 0; mt < 4; mt++) {
        int r0 = row0 + wm + mt * 16 + g;
#pragma unroll
        for (int nt = 0; nt < 4; nt++) {
            int col = col0 + wn + nt * 8 + 2 * qc;
            float b0 = bias[col], b1 = bias[col + 1];
#pragma unroll
            for (int half = 0; half < 2; half++) {
                int rrow = r0 + half * 8;
                if (rrow < M) {
                    float vx = acc[mt][nt][half * 2 + 0] + b0;
                    float vy = acc[mt][nt][half * 2 + 1] + b1;
                    if (RELU) { vx = fmaxf(vx, 0.f); vy = fmaxf(vy, 0.f); }
                    if (OUTBF16) {
                        __nv_bfloat162 v2 = __floats2bfloat162_rn(vx, vy);
                        *(__nv_bfloat162*)((__nv_bfloat16*)Cv + (size_t)rrow * N + col) = v2;
                    } else {
                        *(float2*)((float*)Cv + (size_t)rrow * N + col) = make_float2(vx, vy);
                    }
                }
            }
        }
    }
}

// =====================================================================
// Fused prep: weight transposes -> bf16, src -> bf16, topk.
// =====================================================================
#define PREP_T_BLK   640
#define PREP_F_BLK   5627
#define PREP_K_BLK   704
#define PREP_BLOCKS  (PREP_T_BLK + PREP_F_BLK + PREP_K_BLK)

__global__ void __launch_bounds__(256)
prep_kernel(const float* __restrict__ src,
            const float* __restrict__ Wv, const float* __restrict__ Wo,
            const float* __restrict__ W1, const float* __restrict__ W2,
            const float* __restrict__ m0, const float* __restrict__ m1,
            const float* __restrict__ m2, const float* __restrict__ m3,
            const float* __restrict__ pmw, const float* __restrict__ pmb,
            __nv_bfloat16* __restrict__ WvT, __nv_bfloat16* __restrict__ WoT,
            __nv_bfloat16* __restrict__ W1T, __nv_bfloat16* __restrict__ W2T,
            __nv_bfloat16* __restrict__ srcb)
{
    int bid = blockIdx.x;
    int tid = threadIdx.x;

    if (bid < PREP_T_BLK) {
        __shared__ float t[32][33];
        const float* s; __nv_bfloat16* dst; int R, C, bx, by;
        if (bid < 64)       { s = Wv; dst = WvT; R = 256;  C = 256;  int u = bid;       bx = u & 7;  by = u >> 3; }
        else if (bid < 128) { s = Wo; dst = WoT; R = 256;  C = 256;  int u = bid - 64;  bx = u & 7;  by = u >> 3; }
        else if (bid < 384) { s = W1; dst = W1T; R = 256;  C = 1024; int u = bid - 128; bx = u & 31; by = u >> 5; }
        else                { s = W2; dst = W2T; R = 1024; C = 256;  int u = bid - 384; bx = u & 7;  by = u >> 3; }
        bx *= 32; by *= 32;
        int tx = tid & 31, ty = tid >> 5;
#pragma unroll
        for (int i = 0; i < 32; i += 8)
            t[ty + i][tx] = s[(size_t)(by + ty + i) * C + bx + tx];
        __syncthreads();
#pragma unroll
        for (int i = 0; i < 32; i += 8)
            dst[(size_t)(bx + ty + i) * R + by + tx] = __float2bfloat16(t[tx][ty + i]);
        return;
    }
    if (bid < PREP_T_BLK + PREP_F_BLK) {
        int i = (bid - PREP_T_BLK) * 256 + tid;
        const int n4 = MROWS * D / 4;
        if (i < n4) {
            float4 v = ((const float4*)src)[i];
            ((__nv_bfloat162*)srcb)[2 * i + 0] = __floats2bfloat162_rn(v.x, v.y);
            ((__nv_bfloat162*)srcb)[2 * i + 1] = __floats2bfloat162_rn(v.z, v.w);
        }
        return;
    }
    int t = (bid - PREP_T_BLK - PREP_F_BLK) * 256 + tid;
    if (t >= MROWS * NH) return;
    int h = t % NH;
    int r = t / NH;
    int q = r % LEN;
    int b = r / LEN;

    int l, Wl, s0;
    const float* mk;
    if (q < 8464)        { l = 0; Wl = 92; s0 = 0;     mk = m0; }
    else if (q < 10580)  { l = 1; Wl = 46; s0 = 8464;  mk = m1; }
    else if (q < 11109)  { l = 2; Wl = 23; s0 = 10580; mk = m2; }
    else                 { l = 3; Wl = 12; s0 = 11109; mk = m3; }
    int Hl = Wl;
    int pos = q - s0;
    int y = pos / Wl, x = pos % Wl;

    float w  = pmw[l * NH + h];
    float bb = pmb[l * NH + h];
    const float* mb = mk + (size_t)b * Hl * Wl;

    float tv[4] = {-1e30f, -1e30f, -1e30f, -1e30f};
    int   ti[4] = {0, 0, 0, 0};

    for (int i = 0; i < 7; i++) {
        int yy = y + i - 3;
        for (int j = 0; j < 7; j++) {
            int xx = x + j - 3;
            float val = 0.0f;
            if (yy >= 0 && yy < Hl && xx >= 0 && xx < Wl)
                val = fmaf(mb[yy * Wl + xx], w, bb);
            if (val > tv[3]) {
                int k = i * 7 + j;
                tv[3] = val; ti[3] = k;
                if (tv[3] > tv[2]) { float fv = tv[2]; tv[2] = tv[3]; tv[3] = fv; int iv = ti[2]; ti[2] = ti[3]; ti[3] = iv; }
                if (tv[2] > tv[1]) { float fv = tv[1]; tv[1] = tv[2]; tv[2] = fv; int iv = ti[1]; ti[1] = ti[2]; ti[2] = iv; }
                if (tv[1] > tv[0]) { float fv = tv[0]; tv[0] = tv[1]; tv[1] = fv; int iv = ti[0]; ti[0] = ti[1]; ti[1] = iv; }
            }
        }
    }

    float mx = tv[0];
    float e0 = expf(tv[0] - mx), e1 = expf(tv[1] - mx),
          e2 = expf(tv[2] - mx), e3 = expf(tv[3] - mx);
    float inv = 1.0f / (4.0f * (e0 + e1 + e2 + e3));

    int base = (r * NH + h) * NP;
    float ee[4] = {e0, e1, e2, e3};
#pragma unroll
    for (int p = 0; p < 4; p++) {
        g_attw[base + p] = ee[p] * inv;
        g_offs[(size_t)(base + p) * 2 + 0] = (float)(ti[p] % 7 - 3);
        g_offs[(size_t)(base + p) * 2 + 1] = (float)(ti[p] / 7 - 3);
    }
}

// =====================================================================
// Deformable sampling: warp = (query, head), bf16 value gathers.
// =====================================================================
__global__ void __launch_bounds__(256)
sample_kernel(const float* __restrict__ ref)
{
    __shared__ int2 s_d[8][16][4];

    int r = blockIdx.x;
    int wid = threadIdx.x >> 5, lane = threadIdx.x & 31;
    int b = r / LEN;

    if (lane < 16) {
        const int HsA[4] = {92, 46, 23, 12};
        const int S0A[4] = {0, 8464, 10580, 11109};
        int l = lane >> 2, p = lane & 3;
        int Wi = HsA[l];
        float Wf = (float)Wi;

        float rx = ref[(size_t)(r * NL + l) * 2 + 0];
        float ry = ref[(size_t)(r * NL + l) * 2 + 1];
        int base = (r * NH + wid) * NP + p;
        float wgt = g_attw[base];
        float ox  = g_offs[(size_t)base * 2 + 0];
        float oy  = g_offs[(size_t)base * 2 + 1];

        float locx = rx + ox / Wf;
        float locy = ry + oy / Wf;
        float xf = locx * Wf - 0.5f;
        float yf = locy * Wf - 0.5f;
        float x0f = floorf(xf), y0f = floorf(yf);
        float tx = xf - x0f, ty = yf - y0f;
        int x0 = (int)x0f, y0 = (int)y0f;
        int x1 = x0 + 1,  y1 = y0 + 1;

        float w00 = (1.0f - tx) * (1.0f - ty) * wgt;
        float w01 = tx * (1.0f - ty) * wgt;
        float w10 = (1.0f - tx) * ty * wgt;
        float w11 = tx * ty * wgt;

        bool vx0 = (x0 >= 0) & (x0 < Wi);
        bool vx1 = (x1 >= 0) & (x1 < Wi);
        bool vy0 = (y0 >= 0) & (y0 < Wi);
        bool vy1 = (y1 >= 0) & (y1 < Wi);

        int x0c = min(max(x0, 0), Wi - 1), x1c = min(max(x1, 0), Wi - 1);
        int y0c = min(max(y0, 0), Wi - 1), y1c = min(max(y1, 0), Wi - 1);
        int rb = b * LEN + S0A[l];

        s_d[wid][lane][0] = make_int2(rb + y0c * Wi + x0c, __float_as_int((vy0 & vx0) ? w00 : 0.0f));
        s_d[wid][lane][1] = make_int2(rb + y0c * Wi + x1c, __float_as_int((vy0 & vx1) ? w01 : 0.0f));
        s_d[wid][lane][2] = make_int2(rb + y1c * Wi + x0c, __float_as_int((vy1 & vx0) ? w10 : 0.0f));
        s_d[wid][lane][3] = make_int2(rb + y1c * Wi + x1c, __float_as_int((vy1 & vx1) ? w11 : 0.0f));
    }
    __syncwarp();

    int j  = lane >> 3;
    int cq = lane & 7;
    const __nv_bfloat16* vb = g_valb + wid * DH + cq * 4;

    float ax = 0.f, ay = 0.f, az = 0.f, aw = 0.f;
#pragma unroll
    for (int c = 0; c < 16; c++) {
        int2 d = s_d[wid][c][j];
        float w = __int_as_float(d.y);
        uint2 raw = *(const uint2*)(vb + (size_t)d.x * D);
        float2 f0 = __bfloat1622float2(*(__nv_bfloat162*)&raw.x);
        float2 f1 = __bfloat1622float2(*(__nv_bfloat162*)&raw.y);
        ax = fmaf(w, f0.x, ax);
        ay = fmaf(w, f0.y, ay);
        az = fmaf(w, f1.x, az);
        aw = fmaf(w, f1.y, aw);
    }
#pragma unroll
    for (int o = 8; o <= 16; o <<= 1) {
        ax += __shfl_xor_sync(0xffffffffu, ax, o);
        ay += __shfl_xor_sync(0xffffffffu, ay, o);
        az += __shfl_xor_sync(0xffffffffu, az, o);
        aw += __shfl_xor_sync(0xffffffffu, aw, o);
    }
    if (lane < 8) {
        __nv_bfloat162 p0 = __floats2bfloat162_rn(ax, ay);
        __nv_bfloat162 p1 = __floats2bfloat162_rn(az, aw);
        uint2 st;
        st.x = *(uint32_t*)&p0;
        st.y = *(uint32_t*)&p1;
        *(uint2*)(g_attnb + (size_t)r * D + wid * DH + cq * 4) = st;
    }
}

// =====================================================================
// out = LayerNorm(a + res) * g + b, float4-vectorized, 4 rows/block.
// =====================================================================
template<int WR>
__global__ void __launch_bounds__(256)
add_ln_kernel(const float4* __restrict__ a, const float4* __restrict__ res,
              const float4* __restrict__ gg, const float4* __restrict__ bb,
              float4* __restrict__ out, __nv_bfloat16* __restrict__ out_r)
{
    int tid = threadIdx.x;
    int rl = tid >> 6;
    int t  = tid & 63;
    int row = blockIdx.x * 4 + rl;
    bool ok = row < MROWS;
    size_t idx = (size_t)row * 64 + t;

    float4 v = make_float4(0.f, 0.f, 0.f, 0.f);
    if (ok) {
        float4 va = a[idx], vr = res[idx];
        v = make_float4(va.x + vr.x, va.y + vr.y, va.z + vr.z, va.w + vr.w);
    }
    float s = v.x + v.y + v.z + v.w;
    float u = v.x * v.x + v.y * v.y + v.z * v.z + v.w * v.w;
#pragma unroll
    for (int o = 16; o; o >>= 1) {
        s += __shfl_xor_sync(0xffffffffu, s, o);
        u += __shfl_xor_sync(0xffffffffu, u, o);
    }
    __shared__ float s1[8], s2[8];
    int w = tid >> 5;
    if ((tid & 31) == 0) { s1[w] = s; s2[w] = u; }
    __syncthreads();
    float sum = s1[rl * 2] + s1[rl * 2 + 1];
    float sq  = s2[rl * 2] + s2[rl * 2 + 1];
    float mean = sum * (1.0f / D);
    float var  = sq * (1.0f / D) - mean * mean;
    float rs = rsqrtf(var + 1e-5f);

    if (ok) {
        float4 g4 = gg[t], b4 = bb[t];
        float4 o;
        o.x = (v.x - mean) * rs * g4.x + b4.x;
        o.y = (v.y - mean) * rs * g4.y + b4.y;
        o.z = (v.z - mean) * rs * g4.z + b4.z;
        o.w = (v.w - mean) * rs * g4.w + b4.w;
        out[idx] = o;
        if (WR) {
            __nv_bfloat162 p0 = __floats2bfloat162_rn(o.x, o.y);
            __nv_bfloat162 p1 = __floats2bfloat162_rn(o.z, o.w);
            uint2 st;
            st.x = *(uint32_t*)&p0;
            st.y = *(uint32_t*)&p1;
            *(uint2*)(out_r + idx * 4) = st;
        }
    }
}

// =====================================================================
extern "C" void kernel_launch(void* const* d_in, const int* in_sizes, int n_in,
                              void* d_out, int out_size)
{
    const float* src  = (const float*)d_in[0];
    const float* ref  = (const float*)d_in[2];
    const float* m0   = (const float*)d_in[4];
    const float* m1   = (const float*)d_in[5];
    const float* m2   = (const float*)d_in[6];
    const float* m3   = (const float*)d_in[7];
    const float* pmw  = (const float*)d_in[10];
    const float* pmb  = (const float*)d_in[11];
    const float* Wv   = (const float*)d_in[12];
    const float* bv   = (const float*)d_in[13];
    const float* Wo   = (const float*)d_in[14];
    const float* bo   = (const float*)d_in[15];
    const float* ln1g = (const float*)d_in[16];
    const float* ln1b = (const float*)d_in[17];
    const float* W1   = (const float*)d_in[18];
    const float* b1   = (const float*)d_in[19];
    const float* W2   = (const float*)d_in[20];
    const float* b2   = (const float*)d_in[21];
    const float* ln2g = (const float*)d_in[22];
    const float* ln2b = (const float*)d_in[23];
    float* out = (float*)d_out;

    float *ptmp, *px;
    __nv_bfloat16 *pvb, *psb, *pab, *pxr, *ph, *pWvT, *pWoT, *pW1T, *pW2T;
    cudaGetSymbolAddress((void**)&pvb,  g_valb);
    cudaGetSymbolAddress((void**)&psb,  g_srcb);
    cudaGetSymbolAddress((void**)&pab,  g_attnb);
    cudaGetSymbolAddress((void**)&ptmp, g_tmp);
    cudaGetSymbolAddress((void**)&px,   g_x);
    cudaGetSymbolAddress((void**)&pxr,  g_xr);
    cudaGetSymbolAddress((void**)&ph,   g_hid);
    cudaGetSymbolAddress((void**)&pWvT, g_WvT);
    cudaGetSymbolAddress((void**)&pWoT, g_WoT);
    cudaGetSymbolAddress((void**)&pW1T, g_W1T);
    cudaGetSymbolAddress((void**)&pW2T, g_W2T);

    cudaFuncSetAttribute((const void*)gemm_bf<0,0>, cudaFuncAttributeMaxDynamicSharedMemorySize, GEMM_SMEM);
    cudaFuncSetAttribute((const void*)gemm_bf<0,1>, cudaFuncAttributeMaxDynamicSharedMemorySize, GEMM_SMEM);
    cudaFuncSetAttribute((const void*)gemm_bf<1,1>, cudaFuncAttributeMaxDynamicSharedMemorySize, GEMM_SMEM);

    const int MB  = (MROWS + 127) / 128;  // 176
    const int LNB = (MROWS + 3) / 4;      // 5627

    // 0. fused prep: weight transposes + src->bf16 + topk
    prep_kernel<<<PREP_BLOCKS, 256>>>(src, Wv, Wo, W1, W2, m0, m1, m2, m3,
                                      pmw, pmb, pWvT, pWoT, pW1T, pW2T, psb);

    // 1. value = src @ Wv + bv  -> bf16
    gemm_bf<0,1><<<dim3(2, MB), 256, GEMM_SMEM>>>(psb, pWvT, bv, pvb, MROWS, 256, 256);

    // 2. deformable bilinear sampling -> bf16 attnout
    sample_kernel<<<MROWS, 256>>>(ref);

    // 3. attn_out = attnout @ Wo + bo  (fp32 out)
    gemm_bf<0,0><<<dim3(2, MB), 256, GEMM_SMEM>>>(pab, pWoT, bo, ptmp, MROWS, 256, 256);

    // 4. x = LN(src + attn_out); fp32 x + bf16 copy
    add_ln_kernel<1><<<LNB, 256>>>((const float4*)ptmp, (const float4*)src,
                                   (const float4*)ln1g, (const float4*)ln1b,
                                   (float4*)px, pxr);

    // 5. hid = relu(x @ W1 + b1) -> bf16
    gemm_bf<1,1><<<dim3(8, MB), 256, GEMM_SMEM>>>(pxr, pW1T, b1, ph, MROWS, 1024, 256);

    // 6. y = hid @ W2 + b2  (fp32 out)
    gemm_bf<0,0><<<dim3(2, MB), 256, GEMM_SMEM>>>(ph, pW2T, b2, ptmp, MROWS, 256, 1024);

    // 7. out = LN(x + y)
    add_ln_kernel<0><<<LNB, 256>>>((const float4*)ptmp, (const float4*)px,
                                   (const float4*)ln2g, (const float4*)ln2b,
                                   (float4*)out, nullptr);
}

// round 12
// speedup vs baseline: 1.0426x; 1.0164x over previous
#include <cuda_runtime.h>
#include <cuda_bf16.h>
#include <cstdint>
#include <math.h>

#define BS   2
#define LEN  11253
#define MROWS (BS*LEN)   // 22506
#define D    256
#define NH   8
#define NP   4
#define NL   4
#define DH   32
#define DFF  1024

// ---- scratch (device globals; no allocation allowed) ----
__device__ __nv_bfloat16  g_valb   [(size_t)MROWS * D];
__device__ __nv_bfloat16  g_srcb   [(size_t)MROWS * D];
__device__ __nv_bfloat16  g_attnb  [(size_t)MROWS * D];
__device__ float          g_tmp    [(size_t)MROWS * D];
__device__ float          g_x      [(size_t)MROWS * D];
__device__ __nv_bfloat16  g_xr     [(size_t)MROWS * D];
__device__ __nv_bfloat16  g_hid    [(size_t)MROWS * DFF];
__device__ float          g_attw   [(size_t)MROWS * NH * NP];
__device__ float          g_offs   [(size_t)MROWS * NH * NP * 2];
__device__ __nv_bfloat16  g_WvT    [D * D];
__device__ __nv_bfloat16  g_WoT    [D * D];
__device__ __nv_bfloat16  g_W1T    [DFF * D];
__device__ __nv_bfloat16  g_W2T    [D * DFF];

// =====================================================================
// helpers
// =====================================================================
__device__ __forceinline__ void mma_bf16(float* d, const uint32_t* a, const uint32_t* b) {
    asm volatile(
        "mma.sync.aligned.m16n8k16.row.col.f32.bf16.bf16.f32 "
        "{%0,%1,%2,%3}, {%4,%5,%6,%7}, {%8,%9}, {%0,%1,%2,%3};"
        : "+f"(d[0]), "+f"(d[1]), "+f"(d[2]), "+f"(d[3])
        : "r"(a[0]), "r"(a[1]), "r"(a[2]), "r"(a[3]), "r"(b[0]), "r"(b[1]));
}
__device__ __forceinline__ void ldsm_x4(uint32_t* r, uint32_t addr) {
    asm volatile("ldmatrix.sync.aligned.m8n8.x4.shared.b16 {%0,%1,%2,%3}, [%4];"
        : "=r"(r[0]), "=r"(r[1]), "=r"(r[2]), "=r"(r[3]) : "r"(addr));
}
__device__ __forceinline__ uint32_t smem_addr_u32(const void* p) {
    uint32_t a;
    asm("{ .reg .u64 t; cvta.to.shared.u64 t, %1; cvt.u32.u64 %0, t; }" : "=r"(a) : "l"(p));
    return a;
}

// =====================================================================
// BF16 tensor-core GEMM, 128x128 tile (for W1 / W2): BK=64, 3-stage,
// 8 warps (2m x 4n), 64x32 warp tile, ldmatrix, 2 CTAs/SM.
// Smem rows: 64 bf16 + 8 pad = 144B; ldsm rows cover all banks.
// =====================================================================
#define ROWB        144                   // bytes per smem row
#define TILE_B      (128*ROWB)            // 18432
#define STAGE_B     (2*TILE_B)            // 36864
#define GEMM_SMEM   (3*STAGE_B)           // 110592

template<int RELU, int OUTBF16>
__global__ void __launch_bounds__(256, 2)
gemm_bf(const __nv_bfloat16* __restrict__ A, const __nv_bfloat16* __restrict__ BT,
        const float* __restrict__ bias, void* __restrict__ Cv,
        int M, int N, int K)
{
    extern __shared__ __align__(16) char smem[];
    int tid = threadIdx.x, wid = tid >> 5, lane = tid & 31;
    int g = lane >> 2, qc = lane & 3;
    int row0 = blockIdx.y * 128, col0 = blockIdx.x * 128;
    int wm = (wid & 1) * 64, wn = (wid >> 1) * 32;

    uint32_t smem_u = smem_addr_u32(smem);
    const int NC = K >> 6;

    auto load_chunk = [&](int c) {
        if (c >= NC) { asm volatile("cp.async.commit_group;"); return; }
        uint32_t a_st = smem_u + (c % 3) * STAGE_B;
        uint32_t b_st = a_st + TILE_B;
        int k0 = c * 64;
        const __nv_bfloat16* Ab = A + (size_t)row0 * K + k0;
        const __nv_bfloat16* Bb = BT + (size_t)col0 * K + k0;
#pragma unroll
        for (int i = 0; i < 4; i++) {
            int f4 = tid + i * 256;
            int r = f4 >> 3, seg = f4 & 7;
            uint32_t off = (uint32_t)(r * ROWB + seg * 16);
            uint32_t nbytes = (row0 + r < M) ? 16u : 0u;
            asm volatile("cp.async.cg.shared.global [%0], [%1], 16, %2;"
                :: "r"(a_st + off), "l"(Ab + (size_t)r * K + seg * 8), "r"(nbytes));
            asm volatile("cp.async.cg.shared.global [%0], [%1], 16;"
                :: "r"(b_st + off), "l"(Bb + (size_t)r * K + seg * 8));
        }
        asm volatile("cp.async.commit_group;");
    };

    float acc[4][4][4];
#pragma unroll
    for (int mt = 0; mt < 4; mt++)
#pragma unroll
        for (int nt = 0; nt < 4; nt++)
#pragma unroll
            for (int i = 0; i < 4; i++) acc[mt][nt][i] = 0.0f;

    int sub = lane >> 3, rr = lane & 7;
    uint32_t a_lrow = (uint32_t)(wm + (sub & 1) * 8 + rr);
    uint32_t a_koff = (uint32_t)((sub >> 1) * 16);
    uint32_t b_lrow = (uint32_t)(wn + (sub >> 1) * 8 + rr);
    uint32_t b_koff = (uint32_t)((sub & 1) * 16);

    load_chunk(0);
    load_chunk(1);

    for (int c = 0; c < NC; c++) {
        if (c + 1 < NC) asm volatile("cp.async.wait_group 1;");
        else            asm volatile("cp.async.wait_group 0;");
        __syncthreads();
        load_chunk(c + 2);

        uint32_t a_base = smem_u + (c % 3) * STAGE_B;
        uint32_t b_base = a_base + TILE_B;
#pragma unroll
        for (int ks = 0; ks < 4; ks++) {
            uint32_t kb = (uint32_t)(ks * 32);
            uint32_t af[4][4];
#pragma unroll
            for (int mt = 0; mt < 4; mt++)
                ldsm_x4(af[mt], a_base + (a_lrow + mt * 16) * ROWB + kb + a_koff);
            uint32_t bf[4][2];
#pragma unroll
            for (int pr = 0; pr < 2; pr++) {
                uint32_t t4[4];
                ldsm_x4(t4, b_base + (b_lrow + pr * 16) * ROWB + kb + b_koff);
                bf[pr * 2 + 0][0] = t4[0]; bf[pr * 2 + 0][1] = t4[1];
                bf[pr * 2 + 1][0] = t4[2]; bf[pr * 2 + 1][1] = t4[3];
            }
#pragma unroll
            for (int mt = 0; mt < 4; mt++)
#pragma unroll
                for (int nt = 0; nt < 4; nt++)
                    mma_bf16(acc[mt][nt], af[mt], bf[nt]);
        }
    }

#pragma unroll
    for (int mt = 0; mt < 4; mt++) {
        int r0 = row0 + wm + mt * 16 + g;
#pragma unroll
        for (int nt = 0; nt < 4; nt++) {
            int col = col0 + wn + nt * 8 + 2 * qc;
            float b0 = bias[col], b1 = bias[col + 1];
#pragma unroll
            for (int half = 0; half < 2; half++) {
                int rrow = r0 + half * 8;
                if (rrow < M) {
                    float vx = acc[mt][nt][half * 2 + 0] + b0;
                    float vy = acc[mt][nt][half * 2 + 1] + b1;
                    if (RELU) { vx = fmaxf(vx, 0.f); vy = fmaxf(vy, 0.f); }
                    if (OUTBF16) {
                        __nv_bfloat162 v2 = __floats2bfloat162_rn(vx, vy);
                        *(__nv_bfloat162*)((__nv_bfloat16*)Cv + (size_t)rrow * N + col) = v2;
                    } else {
                        *(float2*)((float*)Cv + (size_t)rrow * N + col) = make_float2(vx, vy);
                    }
                }
            }
        }
    }
}

// =====================================================================
// BF16 tensor-core GEMM, 64x128 tile (for the short D=256 GEMMs):
// BK=64, 3-stage, 8 warps (2m x 4n), 32x32 warp tile, 2 CTAs/SM.
// Finer tiles -> 704-CTA grid packs waves better (less quantization).
// =====================================================================
#define TILE_A64    (64*ROWB)             // 9216
#define STAGE_B64   (TILE_A64 + TILE_B)   // 27648
#define GEMM64_SMEM (3*STAGE_B64)         // 82944

template<int RELU, int OUTBF16>
__global__ void __launch_bounds__(256, 2)
gemm_bf64(const __nv_bfloat16* __restrict__ A, const __nv_bfloat16* __restrict__ BT,
          const float* __restrict__ bias, void* __restrict__ Cv,
          int M, int N, int K)
{
    extern __shared__ __align__(16) char smem[];
    int tid = threadIdx.x, wid = tid >> 5, lane = tid & 31;
    int g = lane >> 2, qc = lane & 3;
    int row0 = blockIdx.y * 64, col0 = blockIdx.x * 128;
    int wm = (wid & 1) * 32, wn = (wid >> 1) * 32;

    uint32_t smem_u = smem_addr_u32(smem);
    const int NC = K >> 6;

    auto load_chunk = [&](int c) {
        if (c >= NC) { asm volatile("cp.async.commit_group;"); return; }
        uint32_t a_st = smem_u + (c % 3) * STAGE_B64;
        uint32_t b_st = a_st + TILE_A64;
        int k0 = c * 64;
        const __nv_bfloat16* Ab = A + (size_t)row0 * K + k0;
        const __nv_bfloat16* Bb = BT + (size_t)col0 * K + k0;
        // A: 512 segs (2/thread)
#pragma unroll
        for (int i = 0; i < 2; i++) {
            int f4 = tid + i * 256;
            int r = f4 >> 3, seg = f4 & 7;
            uint32_t off = (uint32_t)(r * ROWB + seg * 16);
            uint32_t nbytes = (row0 + r < M) ? 16u : 0u;
            asm volatile("cp.async.cg.shared.global [%0], [%1], 16, %2;"
                :: "r"(a_st + off), "l"(Ab + (size_t)r * K + seg * 8), "r"(nbytes));
        }
        // B: 1024 segs (4/thread)
#pragma unroll
        for (int i = 0; i < 4; i++) {
            int f4 = tid + i * 256;
            int r = f4 >> 3, seg = f4 & 7;
            uint32_t off = (uint32_t)(r * ROWB + seg * 16);
            asm volatile("cp.async.cg.shared.global [%0], [%1], 16;"
                :: "r"(b_st + off), "l"(Bb + (size_t)r * K + seg * 8));
        }
        asm volatile("cp.async.commit_group;");
    };

    float acc[2][4][4];
#pragma unroll
    for (int mt = 0; mt < 2; mt++)
#pragma unroll
        for (int nt = 0; nt < 4; nt++)
#pragma unroll
            for (int i = 0; i < 4; i++) acc[mt][nt][i] = 0.0f;

    int sub = lane >> 3, rr = lane & 7;
    uint32_t a_lrow = (uint32_t)(wm + (sub & 1) * 8 + rr);
    uint32_t a_koff = (uint32_t)((sub >> 1) * 16);
    uint32_t b_lrow = (uint32_t)(wn + (sub >> 1) * 8 + rr);
    uint32_t b_koff = (uint32_t)((sub & 1) * 16);

    load_chunk(0);
    load_chunk(1);

    for (int c = 0; c < NC; c++) {
        if (c + 1 < NC) asm volatile("cp.async.wait_group 1;");
        else            asm volatile("cp.async.wait_group 0;");
        __syncthreads();
        load_chunk(c + 2);

        uint32_t a_base = smem_u + (c % 3) * STAGE_B64;
        uint32_t b_base = a_base + TILE_A64;
#pragma unroll
        for (int ks = 0; ks < 4; ks++) {
            uint32_t kb = (uint32_t)(ks * 32);
            uint32_t af[2][4];
#pragma unroll
            for (int mt = 0; mt < 2; mt++)
                ldsm_x4(af[mt], a_base + (a_lrow + mt * 16) * ROWB + kb + a_koff);
            uint32_t bf[4][2];
#pragma unroll
            for (int pr = 0; pr < 2; pr++) {
                uint32_t t4[4];
                ldsm_x4(t4, b_base + (b_lrow + pr * 16) * ROWB + kb + b_koff);
                bf[pr * 2 + 0][0] = t4[0]; bf[pr * 2 + 0][1] = t4[1];
                bf[pr * 2 + 1][0] = t4[2]; bf[pr * 2 + 1][1] = t4[3];
            }
#pragma unroll
            for (int mt = 0; mt < 2; mt++)
#pragma unroll
                for (int nt = 0; nt < 4; nt++)
                    mma_bf16(acc[mt][nt], af[mt], bf[nt]);
        }
    }

#pragma unroll
    for (int mt = 0; mt < 2; mt++) {
        int r0 = row0 + wm + mt * 16 + g;
#pragma unroll
        for (int nt = 0; nt < 4; nt++) {
            int col = col0 + wn + nt * 8 + 2 * qc;
            float b0 = bias[col], b1 = bias[col + 1];
#pragma unroll
            for (int half = 0; half < 2; half++) {
                int rrow = r0 + half * 8;
                if (rrow < M) {
                    float vx = acc[mt][nt][half * 2 + 0] + b0;
                    float vy = acc[mt][nt][half * 2 + 1] + b1;
                    if (RELU) { vx = fmaxf(vx, 0.f); vy = fmaxf(vy, 0.f); }
                    if (OUTBF16) {
                        __nv_bfloat162 v2 = __floats2bfloat162_rn(vx, vy);
                        *(__nv_bfloat162*)((__nv_bfloat16*)Cv + (size_t)rrow * N + col) = v2;
                    } else {
                        *(float2*)((float*)Cv + (size_t)rrow * N + col) = make_float2(vx, vy);
                    }
                }
            }
        }
    }
}

// =====================================================================
// Fused prep: weight transposes -> bf16, src -> bf16, topk.
// =====================================================================
#define PREP_T_BLK   640
#define PREP_F_BLK   5627
#define PREP_K_BLK   704
#define PREP_BLOCKS  (PREP_T_BLK + PREP_F_BLK + PREP_K_BLK)

__global__ void __launch_bounds__(256)
prep_kernel(const float* __restrict__ src,
            const float* __restrict__ Wv, const float* __restrict__ Wo,
            const float* __restrict__ W1, const float* __restrict__ W2,
            const float* __restrict__ m0, const float* __restrict__ m1,
            const float* __restrict__ m2, const float* __restrict__ m3,
            const float* __restrict__ pmw, const float* __restrict__ pmb,
            __nv_bfloat16* __restrict__ WvT, __nv_bfloat16* __restrict__ WoT,
            __nv_bfloat16* __restrict__ W1T, __nv_bfloat16* __restrict__ W2T,
            __nv_bfloat16* __restrict__ srcb)
{
    int bid = blockIdx.x;
    int tid = threadIdx.x;

    if (bid < PREP_T_BLK) {
        __shared__ float t[32][33];
        const float* s; __nv_bfloat16* dst; int R, C, bx, by;
        if (bid < 64)       { s = Wv; dst = WvT; R = 256;  C = 256;  int u = bid;       bx = u & 7;  by = u >> 3; }
        else if (bid < 128) { s = Wo; dst = WoT; R = 256;  C = 256;  int u = bid - 64;  bx = u & 7;  by = u >> 3; }
        else if (bid < 384) { s = W1; dst = W1T; R = 256;  C = 1024; int u = bid - 128; bx = u & 31; by = u >> 5; }
        else                { s = W2; dst = W2T; R = 1024; C = 256;  int u = bid - 384; bx = u & 7;  by = u >> 3; }
        bx *= 32; by *= 32;
        int tx = tid & 31, ty = tid >> 5;
#pragma unroll
        for (int i = 0; i < 32; i += 8)
            t[ty + i][tx] = s[(size_t)(by + ty + i) * C + bx + tx];
        __syncthreads();
#pragma unroll
        for (int i = 0; i < 32; i += 8)
            dst[(size_t)(bx + ty + i) * R + by + tx] = __float2bfloat16(t[tx][ty + i]);
        return;
    }
    if (bid < PREP_T_BLK + PREP_F_BLK) {
        int i = (bid - PREP_T_BLK) * 256 + tid;
        const int n4 = MROWS * D / 4;
        if (i < n4) {
            float4 v = ((const float4*)src)[i];
            ((__nv_bfloat162*)srcb)[2 * i + 0] = __floats2bfloat162_rn(v.x, v.y);
            ((__nv_bfloat162*)srcb)[2 * i + 1] = __floats2bfloat162_rn(v.z, v.w);
        }
        return;
    }
    int t = (bid - PREP_T_BLK - PREP_F_BLK) * 256 + tid;
    if (t >= MROWS * NH) return;
    int h = t % NH;
    int r = t / NH;
    int q = r % LEN;
    int b = r / LEN;

    int l, Wl, s0;
    const float* mk;
    if (q < 8464)        { l = 0; Wl = 92; s0 = 0;     mk = m0; }
    else if (q < 10580)  { l = 1; Wl = 46; s0 = 8464;  mk = m1; }
    else if (q < 11109)  { l = 2; Wl = 23; s0 = 10580; mk = m2; }
    else                 { l = 3; Wl = 12; s0 = 11109; mk = m3; }
    int Hl = Wl;
    int pos = q - s0;
    int y = pos / Wl, x = pos % Wl;

    float w  = pmw[l * NH + h];
    float bb = pmb[l * NH + h];
    const float* mb = mk + (size_t)b * Hl * Wl;

    float tv[4] = {-1e30f, -1e30f, -1e30f, -1e30f};
    int   ti[4] = {0, 0, 0, 0};

    for (int i = 0; i < 7; i++) {
        int yy = y + i - 3;
        for (int j = 0; j < 7; j++) {
            int xx = x + j - 3;
            float val = 0.0f;
            if (yy >= 0 && yy < Hl && xx >= 0 && xx < Wl)
                val = fmaf(mb[yy * Wl + xx], w, bb);
            if (val > tv[3]) {
                int k = i * 7 + j;
                tv[3] = val; ti[3] = k;
                if (tv[3] > tv[2]) { float fv = tv[2]; tv[2] = tv[3]; tv[3] = fv; int iv = ti[2]; ti[2] = ti[3]; ti[3] = iv; }
                if (tv[2] > tv[1]) { float fv = tv[1]; tv[1] = tv[2]; tv[2] = fv; int iv = ti[1]; ti[1] = ti[2]; ti[2] = iv; }
                if (tv[1] > tv[0]) { float fv = tv[0]; tv[0] = tv[1]; tv[1] = fv; int iv = ti[0]; ti[0] = ti[1]; ti[1] = iv; }
            }
        }
    }

    float mx = tv[0];
    float e0 = expf(tv[0] - mx), e1 = expf(tv[1] - mx),
          e2 = expf(tv[2] - mx), e3 = expf(tv[3] - mx);
    float inv = 1.0f / (4.0f * (e0 + e1 + e2 + e3));

    int base = (r * NH + h) * NP;
    float ee[4] = {e0, e1, e2, e3};
#pragma unroll
    for (int p = 0; p < 4; p++) {
        g_attw[base + p] = ee[p] * inv;
        g_offs[(size_t)(base + p) * 2 + 0] = (float)(ti[p] % 7 - 3);
        g_offs[(size_t)(base + p) * 2 + 1] = (float)(ti[p] / 7 - 3);
    }
}

// =====================================================================
// Deformable sampling: warp = (query, head), bf16 value gathers.
// =====================================================================
__global__ void __launch_bounds__(256)
sample_kernel(const float* __restrict__ ref)
{
    __shared__ int2 s_d[8][16][4];

    int r = blockIdx.x;
    int wid = threadIdx.x >> 5, lane = threadIdx.x & 31;
    int b = r / LEN;

    if (lane < 16) {
        const int HsA[4] = {92, 46, 23, 12};
        const int S0A[4] = {0, 8464, 10580, 11109};
        int l = lane >> 2, p = lane & 3;
        int Wi = HsA[l];
        float Wf = (float)Wi;

        float rx = ref[(size_t)(r * NL + l) * 2 + 0];
        float ry = ref[(size_t)(r * NL + l) * 2 + 1];
        int base = (r * NH + wid) * NP + p;
        float wgt = g_attw[base];
        float ox  = g_offs[(size_t)base * 2 + 0];
        float oy  = g_offs[(size_t)base * 2 + 1];

        float locx = rx + ox / Wf;
        float locy = ry + oy / Wf;
        float xf = locx * Wf - 0.5f;
        float yf = locy * Wf - 0.5f;
        float x0f = floorf(xf), y0f = floorf(yf);
        float tx = xf - x0f, ty = yf - y0f;
        int x0 = (int)x0f, y0 = (int)y0f;
        int x1 = x0 + 1,  y1 = y0 + 1;

        float w00 = (1.0f - tx) * (1.0f - ty) * wgt;
        float w01 = tx * (1.0f - ty) * wgt;
        float w10 = (1.0f - tx) * ty * wgt;
        float w11 = tx * ty * wgt;

        bool vx0 = (x0 >= 0) & (x0 < Wi);
        bool vx1 = (x1 >= 0) & (x1 < Wi);
        bool vy0 = (y0 >= 0) & (y0 < Wi);
        bool vy1 = (y1 >= 0) & (y1 < Wi);

        int x0c = min(max(x0, 0), Wi - 1), x1c = min(max(x1, 0), Wi - 1);
        int y0c = min(max(y0, 0), Wi - 1), y1c = min(max(y1, 0), Wi - 1);
        int rb = b * LEN + S0A[l];

        s_d[wid][lane][0] = make_int2(rb + y0c * Wi + x0c, __float_as_int((vy0 & vx0) ? w00 : 0.0f));
        s_d[wid][lane][1] = make_int2(rb + y0c * Wi + x1c, __float_as_int((vy0 & vx1) ? w01 : 0.0f));
        s_d[wid][lane][2] = make_int2(rb + y1c * Wi + x0c, __float_as_int((vy1 & vx0) ? w10 : 0.0f));
        s_d[wid][lane][3] = make_int2(rb + y1c * Wi + x1c, __float_as_int((vy1 & vx1) ? w11 : 0.0f));
    }
    __syncwarp();

    int j  = lane >> 3;
    int cq = lane & 7;
    const __nv_bfloat16* vb = g_valb + wid * DH + cq * 4;

    float ax = 0.f, ay = 0.f, az = 0.f, aw = 0.f;
#pragma unroll
    for (int c = 0; c < 16; c++) {
        int2 d = s_d[wid][c][j];
        float w = __int_as_float(d.y);
        uint2 raw = *(const uint2*)(vb + (size_t)d.x * D);
        float2 f0 = __bfloat1622float2(*(__nv_bfloat162*)&raw.x);
        float2 f1 = __bfloat1622float2(*(__nv_bfloat162*)&raw.y);
        ax = fmaf(w, f0.x, ax);
        ay = fmaf(w, f0.y, ay);
        az = fmaf(w, f1.x, az);
        aw = fmaf(w, f1.y, aw);
    }
#pragma unroll
    for (int o = 8; o <= 16; o <<= 1) {
        ax += __shfl_xor_sync(0xffffffffu, ax, o);
        ay += __shfl_xor_sync(0xffffffffu, ay, o);
        az += __shfl_xor_sync(0xffffffffu, az, o);
        aw += __shfl_xor_sync(0xffffffffu, aw, o);
    }
    if (lane < 8) {
        __nv_bfloat162 p0 = __floats2bfloat162_rn(ax, ay);
        __nv_bfloat162 p1 = __floats2bfloat162_rn(az, aw);
        uint2 st;
        st.x = *(uint32_t*)&p0;
        st.y = *(uint32_t*)&p1;
        *(uint2*)(g_attnb + (size_t)r * D + wid * DH + cq * 4) = st;
    }
}

// =====================================================================
// out = LayerNorm(a + res) * g + b, float4-vectorized, 4 rows/block.
// =====================================================================
template<int WR>
__global__ void __launch_bounds__(256)
add_ln_kernel(const float4* __restrict__ a, const float4* __restrict__ res,
              const float4* __restrict__ gg, const float4* __restrict__ bb,
              float4* __restrict__ out, __nv_bfloat16* __restrict__ out_r)
{
    int tid = threadIdx.x;
    int rl = tid >> 6;
    int t  = tid & 63;
    int row = blockIdx.x * 4 + rl;
    bool ok = row < MROWS;
    size_t idx = (size_t)row * 64 + t;

    float4 v = make_float4(0.f, 0.f, 0.f, 0.f);
    if (ok) {
        float4 va = a[idx], vr = res[idx];
        v = make_float4(va.x + vr.x, va.y + vr.y, va.z + vr.z, va.w + vr.w);
    }
    float s = v.x + v.y + v.z + v.w;
    float u = v.x * v.x + v.y * v.y + v.z * v.z + v.w * v.w;
#pragma unroll
    for (int o = 16; o; o >>= 1) {
        s += __shfl_xor_sync(0xffffffffu, s, o);
        u += __shfl_xor_sync(0xffffffffu, u, o);
    }
    __shared__ float s1[8], s2[8];
    int w = tid >> 5;
    if ((tid & 31) == 0) { s1[w] = s; s2[w] = u; }
    __syncthreads();
    float sum = s1[rl * 2] + s1[rl * 2 + 1];
    float sq  = s2[rl * 2] + s2[rl * 2 + 1];
    float mean = sum * (1.0f / D);
    float var  = sq * (1.0f / D) - mean * mean;
    float rs = rsqrtf(var + 1e-5f);

    if (ok) {
        float4 g4 = gg[t], b4 = bb[t];
        float4 o;
        o.x = (v.x - mean) * rs * g4.x + b4.x;
        o.y = (v.y - mean) * rs * g4.y + b4.y;
        o.z = (v.z - mean) * rs * g4.z + b4.z;
        o.w = (v.w - mean) * rs * g4.w + b4.w;
        out[idx] = o;
        if (WR) {
            __nv_bfloat162 p0 = __floats2bfloat162_rn(o.x, o.y);
            __nv_bfloat162 p1 = __floats2bfloat162_rn(o.z, o.w);
            uint2 st;
            st.x = *(uint32_t*)&p0;
            st.y = *(uint32_t*)&p1;
            *(uint2*)(out_r + idx * 4) = st;
        }
    }
}

// =====================================================================
extern "C" void kernel_launch(void* const* d_in, const int* in_sizes, int n_in,
                              void* d_out, int out_size)
{
    const float* src  = (const float*)d_in[0];
    const float* ref  = (const float*)d_in[2];
    const float* m0   = (const float*)d_in[4];
    const float* m1   = (const float*)d_in[5];
    const float* m2   = (const float*)d_in[6];
    const float* m3   = (const float*)d_in[7];
    const float* pmw  = (const float*)d_in[10];
    const float* pmb  = (const float*)d_in[11];
    const float* Wv   = (const float*)d_in[12];
    const float* bv   = (const float*)d_in[13];
    const float* Wo   = (const float*)d_in[14];
    const float* bo   = (const float*)d_in[15];
    const float* ln1g = (const float*)d_in[16];
    const float* ln1b = (const float*)d_in[17];
    const float* W1   = (const float*)d_in[18];
    const float* b1   = (const float*)d_in[19];
    const float* W2   = (const float*)d_in[20];
    const float* b2   = (const float*)d_in[21];
    const float* ln2g = (const float*)d_in[22];
    const float* ln2b = (const float*)d_in[23];
    float* out = (float*)d_out;

    float *ptmp, *px;
    __nv_bfloat16 *pvb, *psb, *pab, *pxr, *ph, *pWvT, *pWoT, *pW1T, *pW2T;
    cudaGetSymbolAddress((void**)&pvb,  g_valb);
    cudaGetSymbolAddress((void**)&psb,  g_srcb);
    cudaGetSymbolAddress((void**)&pab,  g_attnb);
    cudaGetSymbolAddress((void**)&ptmp, g_tmp);
    cudaGetSymbolAddress((void**)&px,   g_x);
    cudaGetSymbolAddress((void**)&pxr,  g_xr);
    cudaGetSymbolAddress((void**)&ph,   g_hid);
    cudaGetSymbolAddress((void**)&pWvT, g_WvT);
    cudaGetSymbolAddress((void**)&pWoT, g_WoT);
    cudaGetSymbolAddress((void**)&pW1T, g_W1T);
    cudaGetSymbolAddress((void**)&pW2T, g_W2T);

    cudaFuncSetAttribute((const void*)gemm_bf<0,0>,   cudaFuncAttributeMaxDynamicSharedMemorySize, GEMM_SMEM);
    cudaFuncSetAttribute((const void*)gemm_bf<1,1>,   cudaFuncAttributeMaxDynamicSharedMemorySize, GEMM_SMEM);
    cudaFuncSetAttribute((const void*)gemm_bf64<0,0>, cudaFuncAttributeMaxDynamicSharedMemorySize, GEMM64_SMEM);
    cudaFuncSetAttribute((const void*)gemm_bf64<0,1>, cudaFuncAttributeMaxDynamicSharedMemorySize, GEMM64_SMEM);

    const int MB  = (MROWS + 127) / 128;  // 176
    const int MB64 = (MROWS + 63) / 64;   // 352
    const int LNB = (MROWS + 3) / 4;      // 5627

    // 0. fused prep: weight transposes + src->bf16 + topk
    prep_kernel<<<PREP_BLOCKS, 256>>>(src, Wv, Wo, W1, W2, m0, m1, m2, m3,
                                      pmw, pmb, pWvT, pWoT, pW1T, pW2T, psb);

    // 1. value = src @ Wv + bv  -> bf16   (64-row tiles: better wave packing)
    gemm_bf64<0,1><<<dim3(2, MB64), 256, GEMM64_SMEM>>>(psb, pWvT, bv, pvb, MROWS, 256, 256);

    // 2. deformable bilinear sampling -> bf16 attnout
    sample_kernel<<<MROWS, 256>>>(ref);

    // 3. attn_out = attnout @ Wo + bo  (fp32 out, 64-row tiles)
    gemm_bf64<0,0><<<dim3(2, MB64), 256, GEMM64_SMEM>>>(pab, pWoT, bo, ptmp, MROWS, 256, 256);

    // 4. x = LN(src + attn_out); fp32 x + bf16 copy
    add_ln_kernel<1><<<LNB, 256>>>((const float4*)ptmp, (const float4*)src,
                                   (const float4*)ln1g, (const float4*)ln1b,
                                   (float4*)px, pxr);

    // 5. hid = relu(x @ W1 + b1) -> bf16  (128-tile: B-traffic friendly)
    gemm_bf<1,1><<<dim3(8, MB), 256, GEMM_SMEM>>>(pxr, pW1T, b1, ph, MROWS, 1024, 256);

    // 6. y = hid @ W2 + b2  (fp32 out, 128-tile: K=1024, L2-traffic bound)
    gemm_bf<0,0><<<dim3(2, MB), 256, GEMM_SMEM>>>(ph, pW2T, b2, ptmp, MROWS, 256, 1024);

    // 7. out = LN(x + y)
    add_ln_kernel<0><<<LNB, 256>>>((const float4*)ptmp, (const float4*)px,
                                   (const float4*)ln2g, (const float4*)ln2b,
                                   (float4*)out, nullptr);
}

// round 13
// speedup vs baseline: 1.0481x; 1.0054x over previous
#include <cuda_runtime.h>
#include <cuda_bf16.h>
#include <cstdint>
#include <math.h>

#define BS   2
#define LEN  11253
#define MROWS (BS*LEN)   // 22506
#define D    256
#define NH   8
#define NP   4
#define NL   4
#define DH   32
#define DFF  1024

// ---- scratch (device globals; no allocation allowed) ----
__device__ __nv_bfloat16  g_valb   [(size_t)MROWS * D];
__device__ __nv_bfloat16  g_srcb   [(size_t)MROWS * D];
__device__ __nv_bfloat16  g_attnb  [(size_t)MROWS * D];
__device__ float          g_tmp    [(size_t)MROWS * D];
__device__ float          g_x      [(size_t)MROWS * D];
__device__ __nv_bfloat16  g_xr     [(size_t)MROWS * D];
__device__ __nv_bfloat16  g_hid    [(size_t)MROWS * DFF];
__device__ float          g_attw   [(size_t)MROWS * NH * NP];
__device__ float          g_offs   [(size_t)MROWS * NH * NP * 2];
__device__ __nv_bfloat16  g_WvT    [D * D];
__device__ __nv_bfloat16  g_WoT    [D * D];
__device__ __nv_bfloat16  g_W1T    [DFF * D];
__device__ __nv_bfloat16  g_W2T    [D * DFF];

// =====================================================================
// helpers
// =====================================================================
__device__ __forceinline__ void mma_bf16(float* d, const uint32_t* a, const uint32_t* b) {
    asm volatile(
        "mma.sync.aligned.m16n8k16.row.col.f32.bf16.bf16.f32 "
        "{%0,%1,%2,%3}, {%4,%5,%6,%7}, {%8,%9}, {%0,%1,%2,%3};"
        : "+f"(d[0]), "+f"(d[1]), "+f"(d[2]), "+f"(d[3])
        : "r"(a[0]), "r"(a[1]), "r"(a[2]), "r"(a[3]), "r"(b[0]), "r"(b[1]));
}
__device__ __forceinline__ void ldsm_x4(uint32_t* r, uint32_t addr) {
    asm volatile("ldmatrix.sync.aligned.m8n8.x4.shared.b16 {%0,%1,%2,%3}, [%4];"
        : "=r"(r[0]), "=r"(r[1]), "=r"(r[2]), "=r"(r[3]) : "r"(addr));
}
__device__ __forceinline__ uint32_t smem_addr_u32(const void* p) {
    uint32_t a;
    asm("{ .reg .u64 t; cvta.to.shared.u64 t, %1; cvt.u32.u64 %0, t; }" : "=r"(a) : "l"(p));
    return a;
}

// =====================================================================
// BF16 tensor-core GEMM, 128x128 tile (for W1): BK=64, 3-stage,
// 8 warps (2m x 4n), 64x32 warp tile, ldmatrix, 2 CTAs/SM.
// Smem rows: 64 bf16 + 8 pad = 144B; ldsm rows cover all banks.
// =====================================================================
#define ROWB        144                   // bytes per smem row
#define TILE_B      (128*ROWB)            // 18432
#define STAGE_B     (2*TILE_B)            // 36864
#define GEMM_SMEM   (3*STAGE_B)           // 110592

template<int RELU, int OUTBF16>
__global__ void __launch_bounds__(256, 2)
gemm_bf(const __nv_bfloat16* __restrict__ A, const __nv_bfloat16* __restrict__ BT,
        const float* __restrict__ bias, void* __restrict__ Cv,
        int M, int N, int K)
{
    extern __shared__ __align__(16) char smem[];
    int tid = threadIdx.x, wid = tid >> 5, lane = tid & 31;
    int g = lane >> 2, qc = lane & 3;
    int row0 = blockIdx.y * 128, col0 = blockIdx.x * 128;
    int wm = (wid & 1) * 64, wn = (wid >> 1) * 32;

    uint32_t smem_u = smem_addr_u32(smem);
    const int NC = K >> 6;

    auto load_chunk = [&](int c) {
        if (c >= NC) { asm volatile("cp.async.commit_group;"); return; }
        uint32_t a_st = smem_u + (c % 3) * STAGE_B;
        uint32_t b_st = a_st + TILE_B;
        int k0 = c * 64;
        const __nv_bfloat16* Ab = A + (size_t)row0 * K + k0;
        const __nv_bfloat16* Bb = BT + (size_t)col0 * K + k0;
#pragma unroll
        for (int i = 0; i < 4; i++) {
            int f4 = tid + i * 256;
            int r = f4 >> 3, seg = f4 & 7;
            uint32_t off = (uint32_t)(r * ROWB + seg * 16);
            uint32_t nbytes = (row0 + r < M) ? 16u : 0u;
            asm volatile("cp.async.cg.shared.global [%0], [%1], 16, %2;"
                :: "r"(a_st + off), "l"(Ab + (size_t)r * K + seg * 8), "r"(nbytes));
            asm volatile("cp.async.cg.shared.global [%0], [%1], 16;"
                :: "r"(b_st + off), "l"(Bb + (size_t)r * K + seg * 8));
        }
        asm volatile("cp.async.commit_group;");
    };

    float acc[4][4][4];
#pragma unroll
    for (int mt = 0; mt < 4; mt++)
#pragma unroll
        for (int nt = 0; nt < 4; nt++)
#pragma unroll
            for (int i = 0; i < 4; i++) acc[mt][nt][i] = 0.0f;

    int sub = lane >> 3, rr = lane & 7;
    uint32_t a_lrow = (uint32_t)(wm + (sub & 1) * 8 + rr);
    uint32_t a_koff = (uint32_t)((sub >> 1) * 16);
    uint32_t b_lrow = (uint32_t)(wn + (sub >> 1) * 8 + rr);
    uint32_t b_koff = (uint32_t)((sub & 1) * 16);

    load_chunk(0);
    load_chunk(1);

    for (int c = 0; c < NC; c++) {
        asm volatile("cp.async.wait_group 1;");
        __syncthreads();
        load_chunk(c + 2);

        uint32_t a_base = smem_u + (c % 3) * STAGE_B;
        uint32_t b_base = a_base + TILE_B;
#pragma unroll
        for (int ks = 0; ks < 4; ks++) {
            uint32_t kb = (uint32_t)(ks * 32);
            uint32_t af[4][4];
#pragma unroll
            for (int mt = 0; mt < 4; mt++)
                ldsm_x4(af[mt], a_base + (a_lrow + mt * 16) * ROWB + kb + a_koff);
            uint32_t bf[4][2];
#pragma unroll
            for (int pr = 0; pr < 2; pr++) {
                uint32_t t4[4];
                ldsm_x4(t4, b_base + (b_lrow + pr * 16) * ROWB + kb + b_koff);
                bf[pr * 2 + 0][0] = t4[0]; bf[pr * 2 + 0][1] = t4[1];
                bf[pr * 2 + 1][0] = t4[2]; bf[pr * 2 + 1][1] = t4[3];
            }
#pragma unroll
            for (int mt = 0; mt < 4; mt++)
#pragma unroll
                for (int nt = 0; nt < 4; nt++)
                    mma_bf16(acc[mt][nt], af[mt], bf[nt]);
        }
    }

#pragma unroll
    for (int mt = 0; mt < 4; mt++) {
        int r0 = row0 + wm + mt * 16 + g;
#pragma unroll
        for (int nt = 0; nt < 4; nt++) {
            int col = col0 + wn + nt * 8 + 2 * qc;
            float b0 = bias[col], b1 = bias[col + 1];
#pragma unroll
            for (int half = 0; half < 2; half++) {
                int rrow = r0 + half * 8;
                if (rrow < M) {
                    float vx = acc[mt][nt][half * 2 + 0] + b0;
                    float vy = acc[mt][nt][half * 2 + 1] + b1;
                    if (RELU) { vx = fmaxf(vx, 0.f); vy = fmaxf(vy, 0.f); }
                    if (OUTBF16) {
                        __nv_bfloat162 v2 = __floats2bfloat162_rn(vx, vy);
                        *(__nv_bfloat162*)((__nv_bfloat16*)Cv + (size_t)rrow * N + col) = v2;
                    } else {
                        *(float2*)((float*)Cv + (size_t)rrow * N + col) = make_float2(vx, vy);
                    }
                }
            }
        }
    }
}

// =====================================================================
// BF16 tensor-core GEMM, 64x128 tile, 4-STAGE pipeline (Wv, Wo, W2):
// BK=64, 8 warps (2m x 4n), 32x32 warp tile, 2 CTAs/SM (221KB smem).
// Deeper pipeline + finer tiles: amortizes prologue, packs waves.
// =====================================================================
#define TILE_A64    (64*ROWB)             // 9216
#define STAGE_B64   (TILE_A64 + TILE_B)   // 27648
#define GEMM64_SMEM (4*STAGE_B64)         // 110592

template<int RELU, int OUTBF16>
__global__ void __launch_bounds__(256, 2)
gemm_bf64(const __nv_bfloat16* __restrict__ A, const __nv_bfloat16* __restrict__ BT,
          const float* __restrict__ bias, void* __restrict__ Cv,
          int M, int N, int K)
{
    extern __shared__ __align__(16) char smem[];
    int tid = threadIdx.x, wid = tid >> 5, lane = tid & 31;
    int g = lane >> 2, qc = lane & 3;
    int row0 = blockIdx.y * 64, col0 = blockIdx.x * 128;
    int wm = (wid & 1) * 32, wn = (wid >> 1) * 32;

    uint32_t smem_u = smem_addr_u32(smem);
    const int NC = K >> 6;

    auto load_chunk = [&](int c) {
        if (c >= NC) { asm volatile("cp.async.commit_group;"); return; }
        uint32_t a_st = smem_u + (c & 3) * STAGE_B64;
        uint32_t b_st = a_st + TILE_A64;
        int k0 = c * 64;
        const __nv_bfloat16* Ab = A + (size_t)row0 * K + k0;
        const __nv_bfloat16* Bb = BT + (size_t)col0 * K + k0;
#pragma unroll
        for (int i = 0; i < 2; i++) {
            int f4 = tid + i * 256;
            int r = f4 >> 3, seg = f4 & 7;
            uint32_t off = (uint32_t)(r * ROWB + seg * 16);
            uint32_t nbytes = (row0 + r < M) ? 16u : 0u;
            asm volatile("cp.async.cg.shared.global [%0], [%1], 16, %2;"
                :: "r"(a_st + off), "l"(Ab + (size_t)r * K + seg * 8), "r"(nbytes));
        }
#pragma unroll
        for (int i = 0; i < 4; i++) {
            int f4 = tid + i * 256;
            int r = f4 >> 3, seg = f4 & 7;
            uint32_t off = (uint32_t)(r * ROWB + seg * 16);
            asm volatile("cp.async.cg.shared.global [%0], [%1], 16;"
                :: "r"(b_st + off), "l"(Bb + (size_t)r * K + seg * 8));
        }
        asm volatile("cp.async.commit_group;");
    };

    float acc[2][4][4];
#pragma unroll
    for (int mt = 0; mt < 2; mt++)
#pragma unroll
        for (int nt = 0; nt < 4; nt++)
#pragma unroll
            for (int i = 0; i < 4; i++) acc[mt][nt][i] = 0.0f;

    int sub = lane >> 3, rr = lane & 7;
    uint32_t a_lrow = (uint32_t)(wm + (sub & 1) * 8 + rr);
    uint32_t a_koff = (uint32_t)((sub >> 1) * 16);
    uint32_t b_lrow = (uint32_t)(wn + (sub >> 1) * 8 + rr);
    uint32_t b_koff = (uint32_t)((sub & 1) * 16);

    load_chunk(0);
    load_chunk(1);
    load_chunk(2);

    for (int c = 0; c < NC; c++) {
        asm volatile("cp.async.wait_group 2;");
        __syncthreads();
        load_chunk(c + 3);

        uint32_t a_base = smem_u + (c & 3) * STAGE_B64;
        uint32_t b_base = a_base + TILE_A64;
#pragma unroll
        for (int ks = 0; ks < 4; ks++) {
            uint32_t kb = (uint32_t)(ks * 32);
            uint32_t af[2][4];
#pragma unroll
            for (int mt = 0; mt < 2; mt++)
                ldsm_x4(af[mt], a_base + (a_lrow + mt * 16) * ROWB + kb + a_koff);
            uint32_t bf[4][2];
#pragma unroll
            for (int pr = 0; pr < 2; pr++) {
                uint32_t t4[4];
                ldsm_x4(t4, b_base + (b_lrow + pr * 16) * ROWB + kb + b_koff);
                bf[pr * 2 + 0][0] = t4[0]; bf[pr * 2 + 0][1] = t4[1];
                bf[pr * 2 + 1][0] = t4[2]; bf[pr * 2 + 1][1] = t4[3];
            }
#pragma unroll
            for (int mt = 0; mt < 2; mt++)
#pragma unroll
                for (int nt = 0; nt < 4; nt++)
                    mma_bf16(acc[mt][nt], af[mt], bf[nt]);
        }
    }

#pragma unroll
    for (int mt = 0; mt < 2; mt++) {
        int r0 = row0 + wm + mt * 16 + g;
#pragma unroll
        for (int nt = 0; nt < 4; nt++) {
            int col = col0 + wn + nt * 8 + 2 * qc;
            float b0 = bias[col], b1 = bias[col + 1];
#pragma unroll
            for (int half = 0; half < 2; half++) {
                int rrow = r0 + half * 8;
                if (rrow < M) {
                    float vx = acc[mt][nt][half * 2 + 0] + b0;
                    float vy = acc[mt][nt][half * 2 + 1] + b1;
                    if (RELU) { vx = fmaxf(vx, 0.f); vy = fmaxf(vy, 0.f); }
                    if (OUTBF16) {
                        __nv_bfloat162 v2 = __floats2bfloat162_rn(vx, vy);
                        *(__nv_bfloat162*)((__nv_bfloat16*)Cv + (size_t)rrow * N + col) = v2;
                    } else {
                        *(float2*)((float*)Cv + (size_t)rrow * N + col) = make_float2(vx, vy);
                    }
                }
            }
        }
    }
}

// =====================================================================
// Fused prep: weight transposes -> bf16, src -> bf16, topk.
// =====================================================================
#define PREP_T_BLK   640
#define PREP_F_BLK   5627
#define PREP_K_BLK   704
#define PREP_BLOCKS  (PREP_T_BLK + PREP_F_BLK + PREP_K_BLK)

__global__ void __launch_bounds__(256)
prep_kernel(const float* __restrict__ src,
            const float* __restrict__ Wv, const float* __restrict__ Wo,
            const float* __restrict__ W1, const float* __restrict__ W2,
            const float* __restrict__ m0, const float* __restrict__ m1,
            const float* __restrict__ m2, const float* __restrict__ m3,
            const float* __restrict__ pmw, const float* __restrict__ pmb,
            __nv_bfloat16* __restrict__ WvT, __nv_bfloat16* __restrict__ WoT,
            __nv_bfloat16* __restrict__ W1T, __nv_bfloat16* __restrict__ W2T,
            __nv_bfloat16* __restrict__ srcb)
{
    int bid = blockIdx.x;
    int tid = threadIdx.x;

    if (bid < PREP_T_BLK) {
        __shared__ float t[32][33];
        const float* s; __nv_bfloat16* dst; int R, C, bx, by;
        if (bid < 64)       { s = Wv; dst = WvT; R = 256;  C = 256;  int u = bid;       bx = u & 7;  by = u >> 3; }
        else if (bid < 128) { s = Wo; dst = WoT; R = 256;  C = 256;  int u = bid - 64;  bx = u & 7;  by = u >> 3; }
        else if (bid < 384) { s = W1; dst = W1T; R = 256;  C = 1024; int u = bid - 128; bx = u & 31; by = u >> 5; }
        else                { s = W2; dst = W2T; R = 1024; C = 256;  int u = bid - 384; bx = u & 7;  by = u >> 3; }
        bx *= 32; by *= 32;
        int tx = tid & 31, ty = tid >> 5;
#pragma unroll
        for (int i = 0; i < 32; i += 8)
            t[ty + i][tx] = s[(size_t)(by + ty + i) * C + bx + tx];
        __syncthreads();
#pragma unroll
        for (int i = 0; i < 32; i += 8)
            dst[(size_t)(bx + ty + i) * R + by + tx] = __float2bfloat16(t[tx][ty + i]);
        return;
    }
    if (bid < PREP_T_BLK + PREP_F_BLK) {
        int i = (bid - PREP_T_BLK) * 256 + tid;
        const int n4 = MROWS * D / 4;
        if (i < n4) {
            float4 v = ((const float4*)src)[i];
            ((__nv_bfloat162*)srcb)[2 * i + 0] = __floats2bfloat162_rn(v.x, v.y);
            ((__nv_bfloat162*)srcb)[2 * i + 1] = __floats2bfloat162_rn(v.z, v.w);
        }
        return;
    }
    int t = (bid - PREP_T_BLK - PREP_F_BLK) * 256 + tid;
    if (t >= MROWS * NH) return;
    int h = t % NH;
    int r = t / NH;
    int q = r % LEN;
    int b = r / LEN;

    int l, Wl, s0;
    const float* mk;
    if (q < 8464)        { l = 0; Wl = 92; s0 = 0;     mk = m0; }
    else if (q < 10580)  { l = 1; Wl = 46; s0 = 8464;  mk = m1; }
    else if (q < 11109)  { l = 2; Wl = 23; s0 = 10580; mk = m2; }
    else                 { l = 3; Wl = 12; s0 = 11109; mk = m3; }
    int Hl = Wl;
    int pos = q - s0;
    int y = pos / Wl, x = pos % Wl;

    float w  = pmw[l * NH + h];
    float bb = pmb[l * NH + h];
    const float* mb = mk + (size_t)b * Hl * Wl;

    float tv[4] = {-1e30f, -1e30f, -1e30f, -1e30f};
    int   ti[4] = {0, 0, 0, 0};

    for (int i = 0; i < 7; i++) {
        int yy = y + i - 3;
        for (int j = 0; j < 7; j++) {
            int xx = x + j - 3;
            float val = 0.0f;
            if (yy >= 0 && yy < Hl && xx >= 0 && xx < Wl)
                val = fmaf(mb[yy * Wl + xx], w, bb);
            if (val > tv[3]) {
                int k = i * 7 + j;
                tv[3] = val; ti[3] = k;
                if (tv[3] > tv[2]) { float fv = tv[2]; tv[2] = tv[3]; tv[3] = fv; int iv = ti[2]; ti[2] = ti[3]; ti[3] = iv; }
                if (tv[2] > tv[1]) { float fv = tv[1]; tv[1] = tv[2]; tv[2] = fv; int iv = ti[1]; ti[1] = ti[2]; ti[2] = iv; }
                if (tv[1] > tv[0]) { float fv = tv[0]; tv[0] = tv[1]; tv[1] = fv; int iv = ti[0]; ti[0] = ti[1]; ti[1] = iv; }
            }
        }
    }

    float mx = tv[0];
    float e0 = expf(tv[0] - mx), e1 = expf(tv[1] - mx),
          e2 = expf(tv[2] - mx), e3 = expf(tv[3] - mx);
    float inv = 1.0f / (4.0f * (e0 + e1 + e2 + e3));

    int base = (r * NH + h) * NP;
    float ee[4] = {e0, e1, e2, e3};
#pragma unroll
    for (int p = 0; p < 4; p++) {
        g_attw[base + p] = ee[p] * inv;
        g_offs[(size_t)(base + p) * 2 + 0] = (float)(ti[p] % 7 - 3);
        g_offs[(size_t)(base + p) * 2 + 1] = (float)(ti[p] / 7 - 3);
    }
}

// =====================================================================
// Deformable sampling: warp = (query, head), bf16 value gathers.
// =====================================================================
__global__ void __launch_bounds__(256)
sample_kernel(const float* __restrict__ ref)
{
    __shared__ int2 s_d[8][16][4];

    int r = blockIdx.x;
    int wid = threadIdx.x >> 5, lane = threadIdx.x & 31;
    int b = r / LEN;

    if (lane < 16) {
        const int HsA[4] = {92, 46, 23, 12};
        const int S0A[4] = {0, 8464, 10580, 11109};
        int l = lane >> 2, p = lane & 3;
        int Wi = HsA[l];
        float Wf = (float)Wi;

        float rx = ref[(size_t)(r * NL + l) * 2 + 0];
        float ry = ref[(size_t)(r * NL + l) * 2 + 1];
        int base = (r * NH + wid) * NP + p;
        float wgt = g_attw[base];
        float ox  = g_offs[(size_t)base * 2 + 0];
        float oy  = g_offs[(size_t)base * 2 + 1];

        float locx = rx + ox / Wf;
        float locy = ry + oy / Wf;
        float xf = locx * Wf - 0.5f;
        float yf = locy * Wf - 0.5f;
        float x0f = floorf(xf), y0f = floorf(yf);
        float tx = xf - x0f, ty = yf - y0f;
        int x0 = (int)x0f, y0 = (int)y0f;
        int x1 = x0 + 1,  y1 = y0 + 1;

        float w00 = (1.0f - tx) * (1.0f - ty) * wgt;
        float w01 = tx * (1.0f - ty) * wgt;
        float w10 = (1.0f - tx) * ty * wgt;
        float w11 = tx * ty * wgt;

        bool vx0 = (x0 >= 0) & (x0 < Wi);
        bool vx1 = (x1 >= 0) & (x1 < Wi);
        bool vy0 = (y0 >= 0) & (y0 < Wi);
        bool vy1 = (y1 >= 0) & (y1 < Wi);

        int x0c = min(max(x0, 0), Wi - 1), x1c = min(max(x1, 0), Wi - 1);
        int y0c = min(max(y0, 0), Wi - 1), y1c = min(max(y1, 0), Wi - 1);
        int rb = b * LEN + S0A[l];

        s_d[wid][lane][0] = make_int2(rb + y0c * Wi + x0c, __float_as_int((vy0 & vx0) ? w00 : 0.0f));
        s_d[wid][lane][1] = make_int2(rb + y0c * Wi + x1c, __float_as_int((vy0 & vx1) ? w01 : 0.0f));
        s_d[wid][lane][2] = make_int2(rb + y1c * Wi + x0c, __float_as_int((vy1 & vx0) ? w10 : 0.0f));
        s_d[wid][lane][3] = make_int2(rb + y1c * Wi + x1c, __float_as_int((vy1 & vx1) ? w11 : 0.0f));
    }
    __syncwarp();

    int j  = lane >> 3;
    int cq = lane & 7;
    const __nv_bfloat16* vb = g_valb + wid * DH + cq * 4;

    float ax = 0.f, ay = 0.f, az = 0.f, aw = 0.f;
#pragma unroll
    for (int c = 0; c < 16; c++) {
        int2 d = s_d[wid][c][j];
        float w = __int_as_float(d.y);
        uint2 raw = *(const uint2*)(vb + (size_t)d.x * D);
        float2 f0 = __bfloat1622float2(*(__nv_bfloat162*)&raw.x);
        float2 f1 = __bfloat1622float2(*(__nv_bfloat162*)&raw.y);
        ax = fmaf(w, f0.x, ax);
        ay = fmaf(w, f0.y, ay);
        az = fmaf(w, f1.x, az);
        aw = fmaf(w, f1.y, aw);
    }
#pragma unroll
    for (int o = 8; o <= 16; o <<= 1) {
        ax += __shfl_xor_sync(0xffffffffu, ax, o);
        ay += __shfl_xor_sync(0xffffffffu, ay, o);
        az += __shfl_xor_sync(0xffffffffu, az, o);
        aw += __shfl_xor_sync(0xffffffffu, aw, o);
    }
    if (lane < 8) {
        __nv_bfloat162 p0 = __floats2bfloat162_rn(ax, ay);
        __nv_bfloat162 p1 = __floats2bfloat162_rn(az, aw);
        uint2 st;
        st.x = *(uint32_t*)&p0;
        st.y = *(uint32_t*)&p1;
        *(uint2*)(g_attnb + (size_t)r * D + wid * DH + cq * 4) = st;
    }
}

// =====================================================================
// out = LayerNorm(a + res) * g + b, float4-vectorized, 4 rows/block.
// =====================================================================
template<int WR>
__global__ void __launch_bounds__(256)
add_ln_kernel(const float4* __restrict__ a, const float4* __restrict__ res,
              const float4* __restrict__ gg, const float4* __restrict__ bb,
              float4* __restrict__ out, __nv_bfloat16* __restrict__ out_r)
{
    int tid = threadIdx.x;
    int rl = tid >> 6;
    int t  = tid & 63;
    int row = blockIdx.x * 4 + rl;
    bool ok = row < MROWS;
    size_t idx = (size_t)row * 64 + t;

    float4 v = make_float4(0.f, 0.f, 0.f, 0.f);
    if (ok) {
        float4 va = a[idx], vr = res[idx];
        v = make_float4(va.x + vr.x, va.y + vr.y, va.z + vr.z, va.w + vr.w);
    }
    float s = v.x + v.y + v.z + v.w;
    float u = v.x * v.x + v.y * v.y + v.z * v.z + v.w * v.w;
#pragma unroll
    for (int o = 16; o; o >>= 1) {
        s += __shfl_xor_sync(0xffffffffu, s, o);
        u += __shfl_xor_sync(0xffffffffu, u, o);
    }
    __shared__ float s1[8], s2[8];
    int w = tid >> 5;
    if ((tid & 31) == 0) { s1[w] = s; s2[w] = u; }
    __syncthreads();
    float sum = s1[rl * 2] + s1[rl * 2 + 1];
    float sq  = s2[rl * 2] + s2[rl * 2 + 1];
    float mean = sum * (1.0f / D);
    float var  = sq * (1.0f / D) - mean * mean;
    float rs = rsqrtf(var + 1e-5f);

    if (ok) {
        float4 g4 = gg[t], b4 = bb[t];
        float4 o;
        o.x = (v.x - mean) * rs * g4.x + b4.x;
        o.y = (v.y - mean) * rs * g4.y + b4.y;
        o.z = (v.z - mean) * rs * g4.z + b4.z;
        o.w = (v.w - mean) * rs * g4.w + b4.w;
        out[idx] = o;
        if (WR) {
            __nv_bfloat162 p0 = __floats2bfloat162_rn(o.x, o.y);
            __nv_bfloat162 p1 = __floats2bfloat162_rn(o.z, o.w);
            uint2 st;
            st.x = *(uint32_t*)&p0;
            st.y = *(uint32_t*)&p1;
            *(uint2*)(out_r + idx * 4) = st;
        }
    }
}

// =====================================================================
extern "C" void kernel_launch(void* const* d_in, const int* in_sizes, int n_in,
                              void* d_out, int out_size)
{
    const float* src  = (const float*)d_in[0];
    const float* ref  = (const float*)d_in[2];
    const float* m0   = (const float*)d_in[4];
    const float* m1   = (const float*)d_in[5];
    const float* m2   = (const float*)d_in[6];
    const float* m3   = (const float*)d_in[7];
    const float* pmw  = (const float*)d_in[10];
    const float* pmb  = (const float*)d_in[11];
    const float* Wv   = (const float*)d_in[12];
    const float* bv   = (const float*)d_in[13];
    const float* Wo   = (const float*)d_in[14];
    const float* bo   = (const float*)d_in[15];
    const float* ln1g = (const float*)d_in[16];
    const float* ln1b = (const float*)d_in[17];
    const float* W1   = (const float*)d_in[18];
    const float* b1   = (const float*)d_in[19];
    const float* W2   = (const float*)d_in[20];
    const float* b2   = (const float*)d_in[21];
    const float* ln2g = (const float*)d_in[22];
    const float* ln2b = (const float*)d_in[23];
    float* out = (float*)d_out;

    float *ptmp, *px;
    __nv_bfloat16 *pvb, *psb, *pab, *pxr, *ph, *pWvT, *pWoT, *pW1T, *pW2T;
    cudaGetSymbolAddress((void**)&pvb,  g_valb);
    cudaGetSymbolAddress((void**)&psb,  g_srcb);
    cudaGetSymbolAddress((void**)&pab,  g_attnb);
    cudaGetSymbolAddress((void**)&ptmp, g_tmp);
    cudaGetSymbolAddress((void**)&px,   g_x);
    cudaGetSymbolAddress((void**)&pxr,  g_xr);
    cudaGetSymbolAddress((void**)&ph,   g_hid);
    cudaGetSymbolAddress((void**)&pWvT, g_WvT);
    cudaGetSymbolAddress((void**)&pWoT, g_WoT);
    cudaGetSymbolAddress((void**)&pW1T, g_W1T);
    cudaGetSymbolAddress((void**)&pW2T, g_W2T);

    cudaFuncSetAttribute((const void*)gemm_bf<1,1>,   cudaFuncAttributeMaxDynamicSharedMemorySize, GEMM_SMEM);
    cudaFuncSetAttribute((const void*)gemm_bf64<0,0>, cudaFuncAttributeMaxDynamicSharedMemorySize, GEMM64_SMEM);
    cudaFuncSetAttribute((const void*)gemm_bf64<0,1>, cudaFuncAttributeMaxDynamicSharedMemorySize, GEMM64_SMEM);

    const int MB  = (MROWS + 127) / 128;  // 176
    const int MB64 = (MROWS + 63) / 64;   // 352
    const int LNB = (MROWS + 3) / 4;      // 5627

    // 0. fused prep: weight transposes + src->bf16 + topk
    prep_kernel<<<PREP_BLOCKS, 256>>>(src, Wv, Wo, W1, W2, m0, m1, m2, m3,
                                      pmw, pmb, pWvT, pWoT, pW1T, pW2T, psb);

    // 1. value = src @ Wv + bv  -> bf16   (64-row tiles, 4-stage)
    gemm_bf64<0,1><<<dim3(2, MB64), 256, GEMM64_SMEM>>>(psb, pWvT, bv, pvb, MROWS, 256, 256);

    // 2. deformable bilinear sampling -> bf16 attnout
    sample_kernel<<<MROWS, 256>>>(ref);

    // 3. attn_out = attnout @ Wo + bo  (fp32 out, 64-row tiles, 4-stage)
    gemm_bf64<0,0><<<dim3(2, MB64), 256, GEMM64_SMEM>>>(pab, pWoT, bo, ptmp, MROWS, 256, 256);

    // 4. x = LN(src + attn_out); fp32 x + bf16 copy
    add_ln_kernel<1><<<LNB, 256>>>((const float4*)ptmp, (const float4*)src,
                                   (const float4*)ln1g, (const float4*)ln1b,
                                   (float4*)px, pxr);

    // 5. hid = relu(x @ W1 + b1) -> bf16  (128-tile, 4.8 waves: fine)
    gemm_bf<1,1><<<dim3(8, MB), 256, GEMM_SMEM>>>(pxr, pW1T, b1, ph, MROWS, 1024, 256);

    // 6. y = hid @ W2 + b2  (fp32 out, 64-row tiles, 4-stage: K=1024,
    //    long mainloop amortizes prologue; 2.4 waves pack the tail)
    gemm_bf64<0,0><<<dim3(2, MB64), 256, GEMM64_SMEM>>>(ph, pW2T, b2, ptmp, MROWS, 256, 1024);

    // 7. out = LN(x + y)
    add_ln_kernel<0><<<LNB, 256>>>((const float4*)ptmp, (const float4*)px,
                                   (const float4*)ln2g, (const float4*)ln2b,
                                   (float4*)out, nullptr);
}

// round 14
// speedup vs baseline: 1.0739x; 1.0246x over previous
#include <cuda_runtime.h>
#include <cuda_bf16.h>
#include <cstdint>
#include <math.h>

#define BS   2
#define LEN  11253
#define MROWS (BS*LEN)   // 22506
#define D    256
#define NH   8
#define NP   4
#define NL   4
#define DH   32
#define DFF  1024

// ---- scratch (device globals; no allocation allowed) ----
__device__ __nv_bfloat16  g_valb   [(size_t)MROWS * D];
__device__ __nv_bfloat16  g_srcb   [(size_t)MROWS * D];
__device__ __nv_bfloat16  g_attnb  [(size_t)MROWS * D];
__device__ float          g_tmp    [(size_t)MROWS * D];
__device__ float          g_x      [(size_t)MROWS * D];
__device__ __nv_bfloat16  g_xr     [(size_t)MROWS * D];
__device__ __nv_bfloat16  g_hid    [(size_t)MROWS * DFF];
__device__ float          g_attw   [(size_t)MROWS * NH * NP];
__device__ float          g_offs   [(size_t)MROWS * NH * NP * 2];
__device__ __nv_bfloat16  g_WvT    [D * D];
__device__ __nv_bfloat16  g_WoT    [D * D];
__device__ __nv_bfloat16  g_W1T    [DFF * D];
__device__ __nv_bfloat16  g_W2T    [D * DFF];

// =====================================================================
// helpers
// =====================================================================
__device__ __forceinline__ void mma_bf16(float* d, const uint32_t* a, const uint32_t* b) {
    asm volatile(
        "mma.sync.aligned.m16n8k16.row.col.f32.bf16.bf16.f32 "
        "{%0,%1,%2,%3}, {%4,%5,%6,%7}, {%8,%9}, {%0,%1,%2,%3};"
        : "+f"(d[0]), "+f"(d[1]), "+f"(d[2]), "+f"(d[3])
        : "r"(a[0]), "r"(a[1]), "r"(a[2]), "r"(a[3]), "r"(b[0]), "r"(b[1]));
}
__device__ __forceinline__ void ldsm_x4(uint32_t* r, uint32_t addr) {
    asm volatile("ldmatrix.sync.aligned.m8n8.x4.shared.b16 {%0,%1,%2,%3}, [%4];"
        : "=r"(r[0]), "=r"(r[1]), "=r"(r[2]), "=r"(r[3]) : "r"(addr));
}
__device__ __forceinline__ uint32_t smem_addr_u32(const void* p) {
    uint32_t a;
    asm("{ .reg .u64 t; cvta.to.shared.u64 t, %1; cvt.u32.u64 %0, t; }" : "=r"(a) : "l"(p));
    return a;
}

// =====================================================================
// BF16 tensor-core GEMM, 128x128 tile (for W1): BK=64, 3-stage,
// 8 warps (2m x 4n), 64x32 warp tile, ldmatrix, 2 CTAs/SM.
// Smem rows: 64 bf16 + 8 pad = 144B; ldsm rows cover all banks.
// =====================================================================
#define ROWB        144                   // bytes per smem row
#define TILE_B      (128*ROWB)            // 18432
#define STAGE_B     (2*TILE_B)            // 36864
#define GEMM_SMEM   (3*STAGE_B)           // 110592

template<int RELU, int OUTBF16>
__global__ void __launch_bounds__(256, 2)
gemm_bf(const __nv_bfloat16* __restrict__ A, const __nv_bfloat16* __restrict__ BT,
        const float* __restrict__ bias, void* __restrict__ Cv,
        int M, int N, int K)
{
    extern __shared__ __align__(16) char smem[];
    int tid = threadIdx.x, wid = tid >> 5, lane = tid & 31;
    int g = lane >> 2, qc = lane & 3;
    int row0 = blockIdx.y * 128, col0 = blockIdx.x * 128;
    int wm = (wid & 1) * 64, wn = (wid >> 1) * 32;

    uint32_t smem_u = smem_addr_u32(smem);
    const int NC = K >> 6;

    auto load_chunk = [&](int c) {
        if (c >= NC) { asm volatile("cp.async.commit_group;"); return; }
        uint32_t a_st = smem_u + (c % 3) * STAGE_B;
        uint32_t b_st = a_st + TILE_B;
        int k0 = c * 64;
        const __nv_bfloat16* Ab = A + (size_t)row0 * K + k0;
        const __nv_bfloat16* Bb = BT + (size_t)col0 * K + k0;
#pragma unroll
        for (int i = 0; i < 4; i++) {
            int f4 = tid + i * 256;
            int r = f4 >> 3, seg = f4 & 7;
            uint32_t off = (uint32_t)(r * ROWB + seg * 16);
            uint32_t nbytes = (row0 + r < M) ? 16u : 0u;
            asm volatile("cp.async.cg.shared.global [%0], [%1], 16, %2;"
                :: "r"(a_st + off), "l"(Ab + (size_t)r * K + seg * 8), "r"(nbytes));
            asm volatile("cp.async.cg.shared.global [%0], [%1], 16;"
                :: "r"(b_st + off), "l"(Bb + (size_t)r * K + seg * 8));
        }
        asm volatile("cp.async.commit_group;");
    };

    float acc[4][4][4];
#pragma unroll
    for (int mt = 0; mt < 4; mt++)
#pragma unroll
        for (int nt = 0; nt < 4; nt++)
#pragma unroll
            for (int i = 0; i < 4; i++) acc[mt][nt][i] = 0.0f;

    int sub = lane >> 3, rr = lane & 7;
    uint32_t a_lrow = (uint32_t)(wm + (sub & 1) * 8 + rr);
    uint32_t a_koff = (uint32_t)((sub >> 1) * 16);
    uint32_t b_lrow = (uint32_t)(wn + (sub >> 1) * 8 + rr);
    uint32_t b_koff = (uint32_t)((sub & 1) * 16);

    load_chunk(0);
    load_chunk(1);

    for (int c = 0; c < NC; c++) {
        asm volatile("cp.async.wait_group 1;");
        __syncthreads();
        load_chunk(c + 2);

        uint32_t a_base = smem_u + (c % 3) * STAGE_B;
        uint32_t b_base = a_base + TILE_B;
#pragma unroll
        for (int ks = 0; ks < 4; ks++) {
            uint32_t kb = (uint32_t)(ks * 32);
            uint32_t af[4][4];
#pragma unroll
            for (int mt = 0; mt < 4; mt++)
                ldsm_x4(af[mt], a_base + (a_lrow + mt * 16) * ROWB + kb + a_koff);
            uint32_t bf[4][2];
#pragma unroll
            for (int pr = 0; pr < 2; pr++) {
                uint32_t t4[4];
                ldsm_x4(t4, b_base + (b_lrow + pr * 16) * ROWB + kb + b_koff);
                bf[pr * 2 + 0][0] = t4[0]; bf[pr * 2 + 0][1] = t4[1];
                bf[pr * 2 + 1][0] = t4[2]; bf[pr * 2 + 1][1] = t4[3];
            }
#pragma unroll
            for (int mt = 0; mt < 4; mt++)
#pragma unroll
                for (int nt = 0; nt < 4; nt++)
                    mma_bf16(acc[mt][nt], af[mt], bf[nt]);
        }
    }

#pragma unroll
    for (int mt = 0; mt < 4; mt++) {
        int r0 = row0 + wm + mt * 16 + g;
#pragma unroll
        for (int nt = 0; nt < 4; nt++) {
            int col = col0 + wn + nt * 8 + 2 * qc;
            float b0 = bias[col], b1 = bias[col + 1];
#pragma unroll
            for (int half = 0; half < 2; half++) {
                int rrow = r0 + half * 8;
                if (rrow < M) {
                    float vx = acc[mt][nt][half * 2 + 0] + b0;
                    float vy = acc[mt][nt][half * 2 + 1] + b1;
                    if (RELU) { vx = fmaxf(vx, 0.f); vy = fmaxf(vy, 0.f); }
                    if (OUTBF16) {
                        __nv_bfloat162 v2 = __floats2bfloat162_rn(vx, vy);
                        *(__nv_bfloat162*)((__nv_bfloat16*)Cv + (size_t)rrow * N + col) = v2;
                    } else {
                        *(float2*)((float*)Cv + (size_t)rrow * N + col) = make_float2(vx, vy);
                    }
                }
            }
        }
    }
}

// =====================================================================
// BF16 tensor-core GEMM, 64x128 tile, 2-STAGE double-buffer, 3 CTAs/SM
// (Wv, Wo, W2): BK=64, 8 warps (2m x 4n), 32x32 warp tile.
// Occupancy play: 24 warps/SM hide the exposed per-CTA load latency.
// =====================================================================
#define TILE_A64    (64*ROWB)             // 9216
#define STAGE_B64   (TILE_A64 + TILE_B)   // 27648
#define GEMM64_SMEM (2*STAGE_B64)         // 55296

template<int RELU, int OUTBF16>
__global__ void __launch_bounds__(256, 3)
gemm_bf64(const __nv_bfloat16* __restrict__ A, const __nv_bfloat16* __restrict__ BT,
          const float* __restrict__ bias, void* __restrict__ Cv,
          int M, int N, int K)
{
    extern __shared__ __align__(16) char smem[];
    int tid = threadIdx.x, wid = tid >> 5, lane = tid & 31;
    int g = lane >> 2, qc = lane & 3;
    int row0 = blockIdx.y * 64, col0 = blockIdx.x * 128;
    int wm = (wid & 1) * 32, wn = (wid >> 1) * 32;

    uint32_t smem_u = smem_addr_u32(smem);
    const int NC = K >> 6;

    auto load_chunk = [&](int c) {
        if (c >= NC) return;
        uint32_t a_st = smem_u + (c & 1) * STAGE_B64;
        uint32_t b_st = a_st + TILE_A64;
        int k0 = c * 64;
        const __nv_bfloat16* Ab = A + (size_t)row0 * K + k0;
        const __nv_bfloat16* Bb = BT + (size_t)col0 * K + k0;
#pragma unroll
        for (int i = 0; i < 2; i++) {
            int f4 = tid + i * 256;
            int r = f4 >> 3, seg = f4 & 7;
            uint32_t off = (uint32_t)(r * ROWB + seg * 16);
            uint32_t nbytes = (row0 + r < M) ? 16u : 0u;
            asm volatile("cp.async.cg.shared.global [%0], [%1], 16, %2;"
                :: "r"(a_st + off), "l"(Ab + (size_t)r * K + seg * 8), "r"(nbytes));
        }
#pragma unroll
        for (int i = 0; i < 4; i++) {
            int f4 = tid + i * 256;
            int r = f4 >> 3, seg = f4 & 7;
            uint32_t off = (uint32_t)(r * ROWB + seg * 16);
            asm volatile("cp.async.cg.shared.global [%0], [%1], 16;"
                :: "r"(b_st + off), "l"(Bb + (size_t)r * K + seg * 8));
        }
        asm volatile("cp.async.commit_group;");
    };

    float acc[2][4][4];
#pragma unroll
    for (int mt = 0; mt < 2; mt++)
#pragma unroll
        for (int nt = 0; nt < 4; nt++)
#pragma unroll
            for (int i = 0; i < 4; i++) acc[mt][nt][i] = 0.0f;

    int sub = lane >> 3, rr = lane & 7;
    uint32_t a_lrow = (uint32_t)(wm + (sub & 1) * 8 + rr);
    uint32_t a_koff = (uint32_t)((sub >> 1) * 16);
    uint32_t b_lrow = (uint32_t)(wn + (sub >> 1) * 8 + rr);
    uint32_t b_koff = (uint32_t)((sub & 1) * 16);

    load_chunk(0);

    for (int c = 0; c < NC; c++) {
        asm volatile("cp.async.wait_group 0;");
        __syncthreads();
        load_chunk(c + 1);     // other stage; consumed 2 iterations ago

        uint32_t a_base = smem_u + (c & 1) * STAGE_B64;
        uint32_t b_base = a_base + TILE_A64;
#pragma unroll
        for (int ks = 0; ks < 4; ks++) {
            uint32_t kb = (uint32_t)(ks * 32);
            uint32_t af[2][4];
#pragma unroll
            for (int mt = 0; mt < 2; mt++)
                ldsm_x4(af[mt], a_base + (a_lrow + mt * 16) * ROWB + kb + a_koff);
            uint32_t bf[4][2];
#pragma unroll
            for (int pr = 0; pr < 2; pr++) {
                uint32_t t4[4];
                ldsm_x4(t4, b_base + (b_lrow + pr * 16) * ROWB + kb + b_koff);
                bf[pr * 2 + 0][0] = t4[0]; bf[pr * 2 + 0][1] = t4[1];
                bf[pr * 2 + 1][0] = t4[2]; bf[pr * 2 + 1][1] = t4[3];
            }
#pragma unroll
            for (int mt = 0; mt < 2; mt++)
#pragma unroll
                for (int nt = 0; nt < 4; nt++)
                    mma_bf16(acc[mt][nt], af[mt], bf[nt]);
        }
        __syncthreads();       // all reads of stage c&1 done before next fill
    }

#pragma unroll
    for (int mt = 0; mt < 2; mt++) {
        int r0 = row0 + wm + mt * 16 + g;
#pragma unroll
        for (int nt = 0; nt < 4; nt++) {
            int col = col0 + wn + nt * 8 + 2 * qc;
            float b0 = bias[col], b1 = bias[col + 1];
#pragma unroll
            for (int half = 0; half < 2; half++) {
                int rrow = r0 + half * 8;
                if (rrow < M) {
                    float vx = acc[mt][nt][half * 2 + 0] + b0;
                    float vy = acc[mt][nt][half * 2 + 1] + b1;
                    if (RELU) { vx = fmaxf(vx, 0.f); vy = fmaxf(vy, 0.f); }
                    if (OUTBF16) {
                        __nv_bfloat162 v2 = __floats2bfloat162_rn(vx, vy);
                        *(__nv_bfloat162*)((__nv_bfloat16*)Cv + (size_t)rrow * N + col) = v2;
                    } else {
                        *(float2*)((float*)Cv + (size_t)rrow * N + col) = make_float2(vx, vy);
                    }
                }
            }
        }
    }
}

// =====================================================================
// Fused prep: weight transposes -> bf16, src -> bf16, topk.
// =====================================================================
#define PREP_T_BLK   640
#define PREP_F_BLK   5627
#define PREP_K_BLK   704
#define PREP_BLOCKS  (PREP_T_BLK + PREP_F_BLK + PREP_K_BLK)

__global__ void __launch_bounds__(256)
prep_kernel(const float* __restrict__ src,
            const float* __restrict__ Wv, const float* __restrict__ Wo,
            const float* __restrict__ W1, const float* __restrict__ W2,
            const float* __restrict__ m0, const float* __restrict__ m1,
            const float* __restrict__ m2, const float* __restrict__ m3,
            const float* __restrict__ pmw, const float* __restrict__ pmb,
            __nv_bfloat16* __restrict__ WvT, __nv_bfloat16* __restrict__ WoT,
            __nv_bfloat16* __restrict__ W1T, __nv_bfloat16* __restrict__ W2T,
            __nv_bfloat16* __restrict__ srcb)
{
    int bid = blockIdx.x;
    int tid = threadIdx.x;

    if (bid < PREP_T_BLK) {
        __shared__ float t[32][33];
        const float* s; __nv_bfloat16* dst; int R, C, bx, by;
        if (bid < 64)       { s = Wv; dst = WvT; R = 256;  C = 256;  int u = bid;       bx = u & 7;  by = u >> 3; }
        else if (bid < 128) { s = Wo; dst = WoT; R = 256;  C = 256;  int u = bid - 64;  bx = u & 7;  by = u >> 3; }
        else if (bid < 384) { s = W1; dst = W1T; R = 256;  C = 1024; int u = bid - 128; bx = u & 31; by = u >> 5; }
        else                { s = W2; dst = W2T; R = 1024; C = 256;  int u = bid - 384; bx = u & 7;  by = u >> 3; }
        bx *= 32; by *= 32;
        int tx = tid & 31, ty = tid >> 5;
#pragma unroll
        for (int i = 0; i < 32; i += 8)
            t[ty + i][tx] = s[(size_t)(by + ty + i) * C + bx + tx];
        __syncthreads();
#pragma unroll
        for (int i = 0; i < 32; i += 8)
            dst[(size_t)(bx + ty + i) * R + by + tx] = __float2bfloat16(t[tx][ty + i]);
        return;
    }
    if (bid < PREP_T_BLK + PREP_F_BLK) {
        int i = (bid - PREP_T_BLK) * 256 + tid;
        const int n4 = MROWS * D / 4;
        if (i < n4) {
            float4 v = ((const float4*)src)[i];
            ((__nv_bfloat162*)srcb)[2 * i + 0] = __floats2bfloat162_rn(v.x, v.y);
            ((__nv_bfloat162*)srcb)[2 * i + 1] = __floats2bfloat162_rn(v.z, v.w);
        }
        return;
    }
    int t = (bid - PREP_T_BLK - PREP_F_BLK) * 256 + tid;
    if (t >= MROWS * NH) return;
    int h = t % NH;
    int r = t / NH;
    int q = r % LEN;
    int b = r / LEN;

    int l, Wl, s0;
    const float* mk;
    if (q < 8464)        { l = 0; Wl = 92; s0 = 0;     mk = m0; }
    else if (q < 10580)  { l = 1; Wl = 46; s0 = 8464;  mk = m1; }
    else if (q < 11109)  { l = 2; Wl = 23; s0 = 10580; mk = m2; }
    else                 { l = 3; Wl = 12; s0 = 11109; mk = m3; }
    int Hl = Wl;
    int pos = q - s0;
    int y = pos / Wl, x = pos % Wl;

    float w  = pmw[l * NH + h];
    float bb = pmb[l * NH + h];
    const float* mb = mk + (size_t)b * Hl * Wl;

    float tv[4] = {-1e30f, -1e30f, -1e30f, -1e30f};
    int   ti[4] = {0, 0, 0, 0};

    for (int i = 0; i < 7; i++) {
        int yy = y + i - 3;
        for (int j = 0; j < 7; j++) {
            int xx = x + j - 3;
            float val = 0.0f;
            if (yy >= 0 && yy < Hl && xx >= 0 && xx < Wl)
                val = fmaf(mb[yy * Wl + xx], w, bb);
            if (val > tv[3]) {
                int k = i * 7 + j;
                tv[3] = val; ti[3] = k;
                if (tv[3] > tv[2]) { float fv = tv[2]; tv[2] = tv[3]; tv[3] = fv; int iv = ti[2]; ti[2] = ti[3]; ti[3] = iv; }
                if (tv[2] > tv[1]) { float fv = tv[1]; tv[1] = tv[2]; tv[2] = fv; int iv = ti[1]; ti[1] = ti[2]; ti[2] = iv; }
                if (tv[1] > tv[0]) { float fv = tv[0]; tv[0] = tv[1]; tv[1] = fv; int iv = ti[0]; ti[0] = ti[1]; ti[1] = iv; }
            }
        }
    }

    float mx = tv[0];
    float e0 = expf(tv[0] - mx), e1 = expf(tv[1] - mx),
          e2 = expf(tv[2] - mx), e3 = expf(tv[3] - mx);
    float inv = 1.0f / (4.0f * (e0 + e1 + e2 + e3));

    int base = (r * NH + h) * NP;
    float ee[4] = {e0, e1, e2, e3};
#pragma unroll
    for (int p = 0; p < 4; p++) {
        g_attw[base + p] = ee[p] * inv;
        g_offs[(size_t)(base + p) * 2 + 0] = (float)(ti[p] % 7 - 3);
        g_offs[(size_t)(base + p) * 2 + 1] = (float)(ti[p] / 7 - 3);
    }
}

// =====================================================================
// Deformable sampling: warp = (query, head), bf16 value gathers.
// =====================================================================
__global__ void __launch_bounds__(256)
sample_kernel(const float* __restrict__ ref)
{
    __shared__ int2 s_d[8][16][4];

    int r = blockIdx.x;
    int wid = threadIdx.x >> 5, lane = threadIdx.x & 31;
    int b = r / LEN;

    if (lane < 16) {
        const int HsA[4] = {92, 46, 23, 12};
        const int S0A[4] = {0, 8464, 10580, 11109};
        int l = lane >> 2, p = lane & 3;
        int Wi = HsA[l];
        float Wf = (float)Wi;

        float rx = ref[(size_t)(r * NL + l) * 2 + 0];
        float ry = ref[(size_t)(r * NL + l) * 2 + 1];
        int base = (r * NH + wid) * NP + p;
        float wgt = g_attw[base];
        float ox  = g_offs[(size_t)base * 2 + 0];
        float oy  = g_offs[(size_t)base * 2 + 1];

        float locx = rx + ox / Wf;
        float locy = ry + oy / Wf;
        float xf = locx * Wf - 0.5f;
        float yf = locy * Wf - 0.5f;
        float x0f = floorf(xf), y0f = floorf(yf);
        float tx = xf - x0f, ty = yf - y0f;
        int x0 = (int)x0f, y0 = (int)y0f;
        int x1 = x0 + 1,  y1 = y0 + 1;

        float w00 = (1.0f - tx) * (1.0f - ty) * wgt;
        float w01 = tx * (1.0f - ty) * wgt;
        float w10 = (1.0f - tx) * ty * wgt;
        float w11 = tx * ty * wgt;

        bool vx0 = (x0 >= 0) & (x0 < Wi);
        bool vx1 = (x1 >= 0) & (x1 < Wi);
        bool vy0 = (y0 >= 0) & (y0 < Wi);
        bool vy1 = (y1 >= 0) & (y1 < Wi);

        int x0c = min(max(x0, 0), Wi - 1), x1c = min(max(x1, 0), Wi - 1);
        int y0c = min(max(y0, 0), Wi - 1), y1c = min(max(y1, 0), Wi - 1);
        int rb = b * LEN + S0A[l];

        s_d[wid][lane][0] = make_int2(rb + y0c * Wi + x0c, __float_as_int((vy0 & vx0) ? w00 : 0.0f));
        s_d[wid][lane][1] = make_int2(rb + y0c * Wi + x1c, __float_as_int((vy0 & vx1) ? w01 : 0.0f));
        s_d[wid][lane][2] = make_int2(rb + y1c * Wi + x0c, __float_as_int((vy1 & vx0) ? w10 : 0.0f));
        s_d[wid][lane][3] = make_int2(rb + y1c * Wi + x1c, __float_as_int((vy1 & vx1) ? w11 : 0.0f));
    }
    __syncwarp();

    int j  = lane >> 3;
    int cq = lane & 7;
    const __nv_bfloat16* vb = g_valb + wid * DH + cq * 4;

    float ax = 0.f, ay = 0.f, az = 0.f, aw = 0.f;
#pragma unroll
    for (int c = 0; c < 16; c++) {
        int2 d = s_d[wid][c][j];
        float w = __int_as_float(d.y);
        uint2 raw = *(const uint2*)(vb + (size_t)d.x * D);
        float2 f0 = __bfloat1622float2(*(__nv_bfloat162*)&raw.x);
        float2 f1 = __bfloat1622float2(*(__nv_bfloat162*)&raw.y);
        ax = fmaf(w, f0.x, ax);
        ay = fmaf(w, f0.y, ay);
        az = fmaf(w, f1.x, az);
        aw = fmaf(w, f1.y, aw);
    }
#pragma unroll
    for (int o = 8; o <= 16; o <<= 1) {
        ax += __shfl_xor_sync(0xffffffffu, ax, o);
        ay += __shfl_xor_sync(0xffffffffu, ay, o);
        az += __shfl_xor_sync(0xffffffffu, az, o);
        aw += __shfl_xor_sync(0xffffffffu, aw, o);
    }
    if (lane < 8) {
        __nv_bfloat162 p0 = __floats2bfloat162_rn(ax, ay);
        __nv_bfloat162 p1 = __floats2bfloat162_rn(az, aw);
        uint2 st;
        st.x = *(uint32_t*)&p0;
        st.y = *(uint32_t*)&p1;
        *(uint2*)(g_attnb + (size_t)r * D + wid * DH + cq * 4) = st;
    }
}

// =====================================================================
// out = LayerNorm(a + res) * g + b, float4-vectorized, 4 rows/block.
// =====================================================================
template<int WR>
__global__ void __launch_bounds__(256)
add_ln_kernel(const float4* __restrict__ a, const float4* __restrict__ res,
              const float4* __restrict__ gg, const float4* __restrict__ bb,
              float4* __restrict__ out, __nv_bfloat16* __restrict__ out_r)
{
    int tid = threadIdx.x;
    int rl = tid >> 6;
    int t  = tid & 63;
    int row = blockIdx.x * 4 + rl;
    bool ok = row < MROWS;
    size_t idx = (size_t)row * 64 + t;

    float4 v = make_float4(0.f, 0.f, 0.f, 0.f);
    if (ok) {
        float4 va = a[idx], vr = res[idx];
        v = make_float4(va.x + vr.x, va.y + vr.y, va.z + vr.z, va.w + vr.w);
    }
    float s = v.x + v.y + v.z + v.w;
    float u = v.x * v.x + v.y * v.y + v.z * v.z + v.w * v.w;
#pragma unroll
    for (int o = 16; o; o >>= 1) {
        s += __shfl_xor_sync(0xffffffffu, s, o);
        u += __shfl_xor_sync(0xffffffffu, u, o);
    }
    __shared__ float s1[8], s2[8];
    int w = tid >> 5;
    if ((tid & 31) == 0) { s1[w] = s; s2[w] = u; }
    __syncthreads();
    float sum = s1[rl * 2] + s1[rl * 2 + 1];
    float sq  = s2[rl * 2] + s2[rl * 2 + 1];
    float mean = sum * (1.0f / D);
    float var  = sq * (1.0f / D) - mean * mean;
    float rs = rsqrtf(var + 1e-5f);

    if (ok) {
        float4 g4 = gg[t], b4 = bb[t];
        float4 o;
        o.x = (v.x - mean) * rs * g4.x + b4.x;
        o.y = (v.y - mean) * rs * g4.y + b4.y;
        o.z = (v.z - mean) * rs * g4.z + b4.z;
        o.w = (v.w - mean) * rs * g4.w + b4.w;
        out[idx] = o;
        if (WR) {
            __nv_bfloat162 p0 = __floats2bfloat162_rn(o.x, o.y);
            __nv_bfloat162 p1 = __floats2bfloat162_rn(o.z, o.w);
            uint2 st;
            st.x = *(uint32_t*)&p0;
            st.y = *(uint32_t*)&p1;
            *(uint2*)(out_r + idx * 4) = st;
        }
    }
}

// =====================================================================
extern "C" void kernel_launch(void* const* d_in, const int* in_sizes, int n_in,
                              void* d_out, int out_size)
{
    const float* src  = (const float*)d_in[0];
    const float* ref  = (const float*)d_in[2];
    const float* m0   = (const float*)d_in[4];
    const float* m1   = (const float*)d_in[5];
    const float* m2   = (const float*)d_in[6];
    const float* m3   = (const float*)d_in[7];
    const float* pmw  = (const float*)d_in[10];
    const float* pmb  = (const float*)d_in[11];
    const float* Wv   = (const float*)d_in[12];
    const float* bv   = (const float*)d_in[13];
    const float* Wo   = (const float*)d_in[14];
    const float* bo   = (const float*)d_in[15];
    const float* ln1g = (const float*)d_in[16];
    const float* ln1b = (const float*)d_in[17];
    const float* W1   = (const float*)d_in[18];
    const float* b1   = (const float*)d_in[19];
    const float* W2   = (const float*)d_in[20];
    const float* b2   = (const float*)d_in[21];
    const float* ln2g = (const float*)d_in[22];
    const float* ln2b = (const float*)d_in[23];
    float* out = (float*)d_out;

    float *ptmp, *px;
    __nv_bfloat16 *pvb, *psb, *pab, *pxr, *ph, *pWvT, *pWoT, *pW1T, *pW2T;
    cudaGetSymbolAddress((void**)&pvb,  g_valb);
    cudaGetSymbolAddress((void**)&psb,  g_srcb);
    cudaGetSymbolAddress((void**)&pab,  g_attnb);
    cudaGetSymbolAddress((void**)&ptmp, g_tmp);
    cudaGetSymbolAddress((void**)&px,   g_x);
    cudaGetSymbolAddress((void**)&pxr,  g_xr);
    cudaGetSymbolAddress((void**)&ph,   g_hid);
    cudaGetSymbolAddress((void**)&pWvT, g_WvT);
    cudaGetSymbolAddress((void**)&pWoT, g_WoT);
    cudaGetSymbolAddress((void**)&pW1T, g_W1T);
    cudaGetSymbolAddress((void**)&pW2T, g_W2T);

    cudaFuncSetAttribute((const void*)gemm_bf<1,1>,   cudaFuncAttributeMaxDynamicSharedMemorySize, GEMM_SMEM);
    cudaFuncSetAttribute((const void*)gemm_bf64<0,0>, cudaFuncAttributeMaxDynamicSharedMemorySize, GEMM64_SMEM);
    cudaFuncSetAttribute((const void*)gemm_bf64<0,1>, cudaFuncAttributeMaxDynamicSharedMemorySize, GEMM64_SMEM);

    const int MB  = (MROWS + 127) / 128;  // 176
    const int MB64 = (MROWS + 63) / 64;   // 352
    const int LNB = (MROWS + 3) / 4;      // 5627

    // 0. fused prep: weight transposes + src->bf16 + topk
    prep_kernel<<<PREP_BLOCKS, 256>>>(src, Wv, Wo, W1, W2, m0, m1, m2, m3,
                                      pmw, pmb, pWvT, pWoT, pW1T, pW2T, psb);

    // 1. value = src @ Wv + bv  -> bf16   (64-tile, 2-stage, 3 CTAs/SM)
    gemm_bf64<0,1><<<dim3(2, MB64), 256, GEMM64_SMEM>>>(psb, pWvT, bv, pvb, MROWS, 256, 256);

    // 2. deformable bilinear sampling -> bf16 attnout
    sample_kernel<<<MROWS, 256>>>(ref);

    // 3. attn_out = attnout @ Wo + bo  (fp32 out)
    gemm_bf64<0,0><<<dim3(2, MB64), 256, GEMM64_SMEM>>>(pab, pWoT, bo, ptmp, MROWS, 256, 256);

    // 4. x = LN(src + attn_out); fp32 x + bf16 copy
    add_ln_kernel<1><<<LNB, 256>>>((const float4*)ptmp, (const float4*)src,
                                   (const float4*)ln1g, (const float4*)ln1b,
                                   (float4*)px, pxr);

    // 5. hid = relu(x @ W1 + b1) -> bf16  (128-tile, 3-stage, 2 CTAs/SM)
    gemm_bf<1,1><<<dim3(8, MB), 256, GEMM_SMEM>>>(pxr, pW1T, b1, ph, MROWS, 1024, 256);

    // 6. y = hid @ W2 + b2  (fp32 out, 64-tile, 2-stage, 3 CTAs/SM)
    gemm_bf64<0,0><<<dim3(2, MB64), 256, GEMM64_SMEM>>>(ph, pW2T, b2, ptmp, MROWS, 256, 1024);

    // 7. out = LN(x + y)
    add_ln_kernel<0><<<LNB, 256>>>((const float4*)ptmp, (const float4*)px,
                                   (const float4*)ln2g, (const float4*)ln2b,
                                   (float4*)out, nullptr);
}